// round 1
// baseline (speedup 1.0000x reference)
#include <cuda_runtime.h>
#include <math.h>

#define DIM_H  128
#define DIM_3H 384
#define MAX_N  50000
#define MAX_E  600000
#define LN_EPS 1e-5f

// Scratch (device globals: allocation-free per harness rules)
__device__ float g_T[MAX_N * DIM_H];        // nodes @ W_msg^T
__device__ float g_msg[MAX_N * DIM_H];      // segment-summed messages
__device__ float g_gi[MAX_N * DIM_3H];      // msg @ w_ih^T + bias2
__device__ float g_gh[MAX_N * DIM_3H];      // nodes @ w_hh^T + b_hh
__device__ float g_colsum[DIM_H];           // column sums of nodes
__device__ float g_bias2[DIM_3H];           // b_ih + w_ih @ mean(nodes)

// ---------------------------------------------------------------------------
// Zero the message accumulator + column-sum accumulator
// ---------------------------------------------------------------------------
__global__ void zero_kernel(int n_nodes) {
    int i = blockIdx.x * blockDim.x + threadIdx.x;
    float4 z = make_float4(0.f, 0.f, 0.f, 0.f);
    int total = n_nodes * (DIM_H / 4);
    if (i < total) reinterpret_cast<float4*>(g_msg)[i] = z;
    if (i < DIM_H / 4) reinterpret_cast<float4*>(g_colsum)[i] = z;
}

// ---------------------------------------------------------------------------
// Column sums of nodes (for the global mean term)
// ---------------------------------------------------------------------------
__global__ void colsum_kernel(const float* __restrict__ nodes, int n_nodes) {
    __shared__ float sh[256];
    int dim = threadIdx.x & 127;
    int sub = threadIdx.x >> 7;
    float acc = 0.f;
    for (int r = blockIdx.x * 2 + sub; r < n_nodes; r += gridDim.x * 2)
        acc += nodes[(size_t)r * DIM_H + dim];
    sh[threadIdx.x] = acc;
    __syncthreads();
    if (sub == 0) atomicAdd(&g_colsum[dim], sh[dim] + sh[dim + 128]);
}

// ---------------------------------------------------------------------------
// bias2 = b_ih + w_ih @ (colsum / n)   (folds the global-mean term into gi)
// ---------------------------------------------------------------------------
__global__ void bias2_kernel(const float* __restrict__ w_ih,
                             const float* __restrict__ b_ih, int n_nodes) {
    __shared__ float mean_s[DIM_H];
    int tid = threadIdx.x;  // 384 threads
    if (tid < DIM_H) mean_s[tid] = g_colsum[tid] * (1.0f / (float)n_nodes);
    __syncthreads();
    float acc = b_ih[tid];
#pragma unroll 8
    for (int k = 0; k < DIM_H; k++)
        acc = fmaf(w_ih[(size_t)tid * DIM_H + k], mean_s[k], acc);
    g_bias2[tid] = acc;
}

// ---------------------------------------------------------------------------
// C[tile 64 rows x 128 cols] = A[n,128] @ W[?,128]^T + bias
// W stored transposed in smem with XOR-by-k swizzle:
//   value W[c][k] lives at  Ws[k*128 + 4*((c>>2) ^ (k&31)) + (c&3)]
// Compute reads (float4 at slot tc ^ (k&31)) are bank-conflict-free.
// ---------------------------------------------------------------------------
__global__ void __launch_bounds__(256)
gemm_nt_kernel(const float* __restrict__ A,
               const float* __restrict__ W,
               const float* __restrict__ bias,
               float* __restrict__ C,
               int n_rows, int ldc) {
    extern __shared__ float sm[];
    float* As = sm;               // [64][128]
    float* Ws = sm + 64 * DIM_H;  // [128][128] swizzled transpose

    const int tid  = threadIdx.x;  // 256
    const int row0 = blockIdx.x * 64;
    const int col0 = blockIdx.y * 128;

    // Load A tile (coalesced float4; zero-fill OOB rows)
    for (int i = tid; i < 64 * 32; i += 256) {
        int r = i >> 5, c4 = i & 31;
        float4 v = make_float4(0.f, 0.f, 0.f, 0.f);
        if (row0 + r < n_rows)
            v = reinterpret_cast<const float4*>(A + (size_t)(row0 + r) * DIM_H)[c4];
        reinterpret_cast<float4*>(As + r * DIM_H)[c4] = v;
    }
    // Load W tile (coalesced row reads), store transposed + swizzled
    for (int i = tid; i < 128 * 32; i += 256) {
        int c = i >> 5, k4 = i & 31;
        float4 v = reinterpret_cast<const float4*>(W + (size_t)(col0 + c) * DIM_H)[k4];
        int slot = c >> 2, off = c & 3;
        int k = k4 * 4;
        Ws[(k + 0) * 128 + ((slot ^ ((k + 0) & 31)) << 2) + off] = v.x;
        Ws[(k + 1) * 128 + ((slot ^ ((k + 1) & 31)) << 2) + off] = v.y;
        Ws[(k + 2) * 128 + ((slot ^ ((k + 2) & 31)) << 2) + off] = v.z;
        Ws[(k + 3) * 128 + ((slot ^ ((k + 3) & 31)) << 2) + off] = v.w;
    }
    __syncthreads();

    const int tc = tid & 31;   // col group: cols col0 + 4*tc .. +3
    const int tr = tid >> 5;   // row group: rows row0 + 8*tr .. +7

    float acc[8][4];
#pragma unroll
    for (int i = 0; i < 8; i++)
#pragma unroll
        for (int j = 0; j < 4; j++) acc[i][j] = 0.f;

#pragma unroll 4
    for (int k = 0; k < DIM_H; k += 4) {
        float wk[16];
        *reinterpret_cast<float4*>(&wk[0])  = *reinterpret_cast<float4*>(
            Ws + (k + 0) * 128 + ((tc ^ ((k + 0) & 31)) << 2));
        *reinterpret_cast<float4*>(&wk[4])  = *reinterpret_cast<float4*>(
            Ws + (k + 1) * 128 + ((tc ^ ((k + 1) & 31)) << 2));
        *reinterpret_cast<float4*>(&wk[8])  = *reinterpret_cast<float4*>(
            Ws + (k + 2) * 128 + ((tc ^ ((k + 2) & 31)) << 2));
        *reinterpret_cast<float4*>(&wk[12]) = *reinterpret_cast<float4*>(
            Ws + (k + 3) * 128 + ((tc ^ ((k + 3) & 31)) << 2));
#pragma unroll
        for (int i = 0; i < 8; i++) {
            float4 av = *reinterpret_cast<float4*>(As + (tr * 8 + i) * 128 + k);
            float aa[4] = {av.x, av.y, av.z, av.w};
#pragma unroll
            for (int t = 0; t < 4; t++)
#pragma unroll
                for (int j = 0; j < 4; j++)
                    acc[i][j] = fmaf(aa[t], wk[t * 4 + j], acc[i][j]);
        }
    }

    float b0 = 0.f, b1 = 0.f, b2 = 0.f, b3 = 0.f;
    if (bias) {
        float4 bv = *reinterpret_cast<const float4*>(bias + col0 + tc * 4);
        b0 = bv.x; b1 = bv.y; b2 = bv.z; b3 = bv.w;
    }
#pragma unroll
    for (int i = 0; i < 8; i++) {
        int r = row0 + tr * 8 + i;
        if (r < n_rows) {
            float4 o = make_float4(acc[i][0] + b0, acc[i][1] + b1,
                                   acc[i][2] + b2, acc[i][3] + b3);
            *reinterpret_cast<float4*>(C + (size_t)r * ldc + col0 + tc * 4) = o;
        }
    }
}

// ---------------------------------------------------------------------------
// Edge scatter: one warp per edge. messages[dst] += T[src] + b_msg
// 16B vector reduction (red.global.add.v4.f32, sm_90+)
// ---------------------------------------------------------------------------
__global__ void scatter_kernel(const int* __restrict__ esrc,
                               const int* __restrict__ edst,
                               const float* __restrict__ b_msg, int n_edges) {
    int gwarp = (blockIdx.x * blockDim.x + threadIdx.x) >> 5;
    int lane  = threadIdx.x & 31;
    if (gwarp >= n_edges) return;
    int s = esrc[gwarp];
    int d = edst[gwarp];
    float4 v = reinterpret_cast<const float4*>(g_T + (size_t)s * DIM_H)[lane];
    float4 b = reinterpret_cast<const float4*>(b_msg)[lane];
    v.x += b.x; v.y += b.y; v.z += b.z; v.w += b.w;
    float* p = g_msg + (size_t)d * DIM_H + lane * 4;
    asm volatile("red.global.add.v4.f32 [%0], {%1, %2, %3, %4};"
                 :: "l"(p), "f"(v.x), "f"(v.y), "f"(v.z), "f"(v.w) : "memory");
}

// ---------------------------------------------------------------------------
// Fused GRU gates + LayerNorm + message residual. One warp per node.
// ---------------------------------------------------------------------------
__device__ __forceinline__ float sigmoidf_(float x) {
    return 1.0f / (1.0f + expf(-x));
}

__global__ void gru_ln_kernel(const float* __restrict__ nodes,
                              const float* __restrict__ gamma,
                              const float* __restrict__ beta,
                              float* __restrict__ out, int n_nodes) {
    int gwarp = (blockIdx.x * blockDim.x + threadIdx.x) >> 5;
    int lane  = threadIdx.x & 31;
    if (gwarp >= n_nodes) return;

    size_t base  = (size_t)gwarp * DIM_H;
    size_t gbase = (size_t)gwarp * DIM_3H;

    float4 h4  = reinterpret_cast<const float4*>(nodes + base)[lane];
    float4 m4  = reinterpret_cast<const float4*>(g_msg + base)[lane];
    float4 ir4 = reinterpret_cast<const float4*>(g_gi + gbase)[lane];
    float4 iz4 = reinterpret_cast<const float4*>(g_gi + gbase + 128)[lane];
    float4 in4 = reinterpret_cast<const float4*>(g_gi + gbase + 256)[lane];
    float4 hr4 = reinterpret_cast<const float4*>(g_gh + gbase)[lane];
    float4 hz4 = reinterpret_cast<const float4*>(g_gh + gbase + 128)[lane];
    float4 hn4 = reinterpret_cast<const float4*>(g_gh + gbase + 256)[lane];

    float hh[4] = {h4.x, h4.y, h4.z, h4.w};
    float ir[4] = {ir4.x, ir4.y, ir4.z, ir4.w};
    float iz[4] = {iz4.x, iz4.y, iz4.z, iz4.w};
    float in_[4]= {in4.x, in4.y, in4.z, in4.w};
    float hr[4] = {hr4.x, hr4.y, hr4.z, hr4.w};
    float hz[4] = {hz4.x, hz4.y, hz4.z, hz4.w};
    float hn[4] = {hn4.x, hn4.y, hn4.z, hn4.w};

    float hx[4];
    float s = 0.f, s2 = 0.f;
#pragma unroll
    for (int c = 0; c < 4; c++) {
        float r = sigmoidf_(ir[c] + hr[c]);
        float z = sigmoidf_(iz[c] + hz[c]);
        float n = tanhf(in_[c] + r * hn[c]);
        hx[c] = (1.0f - z) * n + z * hh[c];
        s  += hx[c];
        s2 += hx[c] * hx[c];
    }
#pragma unroll
    for (int off = 16; off > 0; off >>= 1) {
        s  += __shfl_xor_sync(0xFFFFFFFF, s,  off);
        s2 += __shfl_xor_sync(0xFFFFFFFF, s2, off);
    }
    float mu   = s  * (1.0f / DIM_H);
    float var  = s2 * (1.0f / DIM_H) - mu * mu;
    float rstd = rsqrtf(var + LN_EPS);

    float4 g4 = reinterpret_cast<const float4*>(gamma)[lane];
    float4 b4 = reinterpret_cast<const float4*>(beta)[lane];
    float gg[4] = {g4.x, g4.y, g4.z, g4.w};
    float bb[4] = {b4.x, b4.y, b4.z, b4.w};
    float mm[4] = {m4.x, m4.y, m4.z, m4.w};

    float o[4];
#pragma unroll
    for (int c = 0; c < 4; c++)
        o[c] = gg[c] * (hx[c] - mu) * rstd + bb[c] + mm[c];

    float4 o4 = make_float4(o[0], o[1], o[2], o[3]);
    reinterpret_cast<float4*>(out + base)[lane] = o4;
}

// ---------------------------------------------------------------------------
// Launch
// ---------------------------------------------------------------------------
extern "C" void kernel_launch(void* const* d_in, const int* in_sizes, int n_in,
                              void* d_out, int out_size) {
    const float* nodes = (const float*)d_in[0];
    const float* W_msg = (const float*)d_in[1];
    const float* b_msg = (const float*)d_in[2];
    const float* w_ih  = (const float*)d_in[3];
    const float* w_hh  = (const float*)d_in[4];
    const float* b_ih  = (const float*)d_in[5];
    const float* b_hh  = (const float*)d_in[6];
    const float* gamma = (const float*)d_in[7];
    const float* beta  = (const float*)d_in[8];
    const int*   esrc  = (const int*)d_in[9];
    const int*   edst  = (const int*)d_in[10];
    float* out = (float*)d_out;

    int n_nodes = in_sizes[0] / DIM_H;
    int n_edges = in_sizes[9];

    float *pT, *pMsg, *pGi, *pGh, *pBias2;
    cudaGetSymbolAddress((void**)&pT,     g_T);
    cudaGetSymbolAddress((void**)&pMsg,   g_msg);
    cudaGetSymbolAddress((void**)&pGi,    g_gi);
    cudaGetSymbolAddress((void**)&pGh,    g_gh);
    cudaGetSymbolAddress((void**)&pBias2, g_bias2);

    const int SMEM = (64 * 128 + 128 * 128) * sizeof(float);  // 96 KB
    cudaFuncSetAttribute(gemm_nt_kernel,
                         cudaFuncAttributeMaxDynamicSharedMemorySize, SMEM);

    int rb = (n_nodes + 63) / 64;

    zero_kernel<<<(n_nodes * 32 + 255) / 256, 256>>>(n_nodes);
    colsum_kernel<<<256, 256>>>(nodes, n_nodes);

    // T = nodes @ W_msg^T  (b_msg is added per-edge in the scatter)
    gemm_nt_kernel<<<dim3(rb, 1), 256, SMEM>>>(nodes, W_msg, nullptr, pT,
                                               n_nodes, DIM_H);
    // messages[dst] += T[src] + b_msg
    scatter_kernel<<<(n_edges + 7) / 8, 256>>>(esrc, edst, b_msg, n_edges);

    // bias2 = b_ih + w_ih @ mean(nodes)
    bias2_kernel<<<1, DIM_3H>>>(w_ih, b_ih, n_nodes);

    // gi = messages @ w_ih^T + bias2 ;  gh = nodes @ w_hh^T + b_hh
    gemm_nt_kernel<<<dim3(rb, 3), 256, SMEM>>>(pMsg, w_ih, pBias2, pGi,
                                               n_nodes, DIM_3H);
    gemm_nt_kernel<<<dim3(rb, 3), 256, SMEM>>>(nodes, w_hh, b_hh, pGh,
                                               n_nodes, DIM_3H);

    // GRU gates + LayerNorm + message residual
    gru_ln_kernel<<<(n_nodes + 7) / 8, 256>>>(nodes, gamma, beta, out, n_nodes);
}

// round 3
// speedup vs baseline: 1.5014x; 1.5014x over previous
#include <cuda_runtime.h>
#include <cuda_bf16.h>
#include <math.h>
#include <stdint.h>

#define DIM_H  128
#define DIM_3H 384
#define MAX_N  50000
#define MAX_E  600000
#define LN_EPS 1e-5f

// ---------------------------------------------------------------------------
// Scratch (device globals: allocation-free per harness rules)
// ---------------------------------------------------------------------------
__device__ float g_T[MAX_N * DIM_H];        // nodes @ W_msg^T
__device__ float g_msg[MAX_N * DIM_H];      // segment-summed messages
__device__ float g_gi[MAX_N * DIM_3H];      // msg @ w_ih^T + bias2
__device__ float g_gh[MAX_N * DIM_3H];      // nodes @ w_hh^T + b_hh
__device__ float g_colsum[DIM_H];           // column sums of nodes
__device__ float g_bias2[DIM_3H];           // b_ih + w_ih @ mean(nodes)

// Split-bf16 weights (hi + lo captures ~16 mantissa bits)
__device__ __nv_bfloat16 g_Wm_hi[DIM_H * DIM_H];
__device__ __nv_bfloat16 g_Wm_lo[DIM_H * DIM_H];
__device__ __nv_bfloat16 g_Wih_hi[DIM_3H * DIM_H];
__device__ __nv_bfloat16 g_Wih_lo[DIM_3H * DIM_H];
__device__ __nv_bfloat16 g_Whh_hi[DIM_3H * DIM_H];
__device__ __nv_bfloat16 g_Whh_lo[DIM_3H * DIM_H];

// ---------------------------------------------------------------------------
// PTX helpers (arch-neutral: ldmatrix + mma.sync, sm_80+ — the harness emits
// compute_103 generic PTX, so tcgen05/sm_103a-only instructions are illegal)
// ---------------------------------------------------------------------------
__device__ __forceinline__ uint32_t smem_u32(const void* p) {
    uint32_t a;
    asm("{ .reg .u64 t; cvta.to.shared.u64 t, %1; cvt.u32.u64 %0, t; }"
        : "=r"(a) : "l"(p));
    return a;
}

__device__ __forceinline__ void ldsm_x4(uint32_t& r0, uint32_t& r1,
                                        uint32_t& r2, uint32_t& r3,
                                        uint32_t addr) {
    asm volatile("ldmatrix.sync.aligned.m8n8.x4.shared.b16 {%0,%1,%2,%3}, [%4];"
                 : "=r"(r0), "=r"(r1), "=r"(r2), "=r"(r3) : "r"(addr));
}

__device__ __forceinline__ void mma_bf16(float* d, uint32_t a0, uint32_t a1,
                                         uint32_t a2, uint32_t a3,
                                         uint32_t b0, uint32_t b1) {
    asm volatile(
        "mma.sync.aligned.m16n8k16.row.col.f32.bf16.bf16.f32 "
        "{%0,%1,%2,%3}, {%4,%5,%6,%7}, {%8,%9}, {%0,%1,%2,%3};"
        : "+f"(d[0]), "+f"(d[1]), "+f"(d[2]), "+f"(d[3])
        : "r"(a0), "r"(a1), "r"(a2), "r"(a3), "r"(b0), "r"(b1));
}

// ---------------------------------------------------------------------------
// Small kernels
// ---------------------------------------------------------------------------
__global__ void zero_kernel(int n_nodes) {
    int i = blockIdx.x * blockDim.x + threadIdx.x;
    float4 z = make_float4(0.f, 0.f, 0.f, 0.f);
    int total = n_nodes * (DIM_H / 4);
    if (i < total) reinterpret_cast<float4*>(g_msg)[i] = z;
    if (i < DIM_H / 4) reinterpret_cast<float4*>(g_colsum)[i] = z;
}

__global__ void colsum_kernel(const float* __restrict__ nodes, int n_nodes) {
    __shared__ float sh[256];
    int dim = threadIdx.x & 127;
    int sub = threadIdx.x >> 7;
    float acc = 0.f;
    for (int r = blockIdx.x * 2 + sub; r < n_nodes; r += gridDim.x * 2)
        acc += nodes[(size_t)r * DIM_H + dim];
    sh[threadIdx.x] = acc;
    __syncthreads();
    if (sub == 0) atomicAdd(&g_colsum[dim], sh[dim] + sh[dim + 128]);
}

__global__ void bias2_kernel(const float* __restrict__ w_ih,
                             const float* __restrict__ b_ih, int n_nodes) {
    __shared__ float mean_s[DIM_H];
    int tid = threadIdx.x;  // 384 threads
    if (tid < DIM_H) mean_s[tid] = g_colsum[tid] * (1.0f / (float)n_nodes);
    __syncthreads();
    float acc = b_ih[tid];
#pragma unroll 8
    for (int k = 0; k < DIM_H; k++)
        acc = fmaf(w_ih[(size_t)tid * DIM_H + k], mean_s[k], acc);
    g_bias2[tid] = acc;
}

// Split fp32 weights into bf16 hi/lo
__global__ void split_kernel(const float* __restrict__ src,
                             __nv_bfloat16* __restrict__ hi,
                             __nv_bfloat16* __restrict__ lo, int n) {
    int i = blockIdx.x * blockDim.x + threadIdx.x;
    if (i >= n) return;
    float x = src[i];
    __nv_bfloat16 h = __float2bfloat16(x);
    hi[i] = h;
    lo[i] = __float2bfloat16(x - __bfloat162float(h));
}

// ---------------------------------------------------------------------------
// Tensor-core GEMM (mma.sync bf16, split hi/lo 3-product, fp32 accumulate)
// C[128-row tile, 128-col tile] = A @ B^T + bias
// A fp32 [n_rows,128] split on the fly; B pre-split bf16 [Nout,128].
// ---------------------------------------------------------------------------
#define LDA 136                       // bf16 elems per smem row (272B stride)
#define TILE_B (128 * LDA * 2)        // 34816 bytes per tile
#define SM_AHI  0
#define SM_ALO  (SM_AHI + TILE_B)
#define SM_BHI  (SM_ALO + TILE_B)
#define SM_BLO  (SM_BHI + TILE_B)
#define SM_BIAS (SM_BLO + TILE_B)     // 128 floats
#define SM_TOTAL (SM_BIAS + 512)

__global__ void __launch_bounds__(256, 1)
gemm_tc_kernel(const float* __restrict__ A,
               const __nv_bfloat16* __restrict__ Bhi,
               const __nv_bfloat16* __restrict__ Blo,
               const float* __restrict__ bias,
               float* __restrict__ C,
               int n_rows, int ldc) {
    extern __shared__ char sm[];
    uint32_t smb = smem_u32(sm);
    const int tid = threadIdx.x;
    const int wid = tid >> 5;
    const int lane = tid & 31;
    const int row0 = blockIdx.x * 128;
    const int col0 = blockIdx.y * 128;

    // Bias tile -> smem
    if (tid < 128)
        *reinterpret_cast<float*>(sm + SM_BIAS + tid * 4) =
            bias ? bias[col0 + tid] : 0.f;

    // A tile: load fp32, split to bf16 hi/lo, store [r][k] stride LDA
    for (int i = tid; i < 128 * 32; i += 256) {
        int r = i >> 5, c4 = i & 31, k = c4 * 4;
        float4 v = make_float4(0.f, 0.f, 0.f, 0.f);
        int row = row0 + r;
        if (row < n_rows)
            v = reinterpret_cast<const float4*>(A + (size_t)row * DIM_H)[c4];
        float xs[4] = {v.x, v.y, v.z, v.w};
        uint32_t hb[4], lb[4];
#pragma unroll
        for (int t = 0; t < 4; t++) {
            __nv_bfloat16 h = __float2bfloat16(xs[t]);
            __nv_bfloat16 l = __float2bfloat16(xs[t] - __bfloat162float(h));
            hb[t] = (uint32_t)__bfloat16_as_ushort(h);
            lb[t] = (uint32_t)__bfloat16_as_ushort(l);
        }
        uint32_t off = (uint32_t)(r * LDA + k) * 2;
        *reinterpret_cast<uint2*>(sm + SM_AHI + off) =
            make_uint2(hb[0] | (hb[1] << 16), hb[2] | (hb[3] << 16));
        *reinterpret_cast<uint2*>(sm + SM_ALO + off) =
            make_uint2(lb[0] | (lb[1] << 16), lb[2] | (lb[3] << 16));
    }

    // B tile: bf16 hi/lo from global [Nout,128] row-major -> smem [n][k]
    for (int i = tid; i < 128 * 16; i += 256) {
        int r = i >> 4, g = i & 15;
        size_t gidx = (size_t)(col0 + r) * DIM_H;
        uint4 vh = reinterpret_cast<const uint4*>(Bhi + gidx)[g];
        uint4 vl = reinterpret_cast<const uint4*>(Blo + gidx)[g];
        uint32_t off = (uint32_t)(r * LDA + g * 8) * 2;
        *reinterpret_cast<uint4*>(sm + SM_BHI + off) = vh;
        *reinterpret_cast<uint4*>(sm + SM_BLO + off) = vl;
    }
    __syncthreads();

    // Warp tile: 32 rows x 64 cols. wr in 0..3 (rows), wc in 0..1 (cols).
    const int wr = wid & 3;
    const int wc = wid >> 2;

    // ldmatrix lane-address offsets (bytes, within a tile):
    // A x4: matrices (m0-7,k0-7),(m8-15,k0-7),(m0-7,k8-15),(m8-15,k8-15)
    const int a_m = (lane & 15);
    const int a_k = (lane >> 4) * 8;
    uint32_t offA[2];
#pragma unroll
    for (int mt = 0; mt < 2; mt++)
        offA[mt] = (uint32_t)(((wr * 32 + mt * 16 + a_m) * LDA + a_k) * 2);

    // B x4 for an n-pair: (n0-7,k0-7),(n0-7,k8-15),(n8-15,k0-7),(n8-15,k8-15)
    const int b_n = (lane & 7) + (lane >> 4) * 8;
    const int b_k = ((lane >> 3) & 1) * 8;
    uint32_t offB[4];
#pragma unroll
    for (int p = 0; p < 4; p++)
        offB[p] = (uint32_t)(((wc * 64 + p * 16 + b_n) * LDA + b_k) * 2);

    float acc[2][8][4];
#pragma unroll
    for (int mt = 0; mt < 2; mt++)
#pragma unroll
        for (int nt = 0; nt < 8; nt++)
#pragma unroll
            for (int e = 0; e < 4; e++) acc[mt][nt][e] = 0.f;

    const uint32_t ahi_b = smb + SM_AHI, alo_b = smb + SM_ALO;
    const uint32_t bhi_b = smb + SM_BHI, blo_b = smb + SM_BLO;

#pragma unroll
    for (int ks = 0; ks < 8; ks++) {
        const uint32_t kb = ks * 32;  // 16 bf16 = 32 bytes per k-step

        uint32_t ah[2][4], al[2][4];
#pragma unroll
        for (int mt = 0; mt < 2; mt++) {
            ldsm_x4(ah[mt][0], ah[mt][1], ah[mt][2], ah[mt][3],
                    ahi_b + offA[mt] + kb);
            ldsm_x4(al[mt][0], al[mt][1], al[mt][2], al[mt][3],
                    alo_b + offA[mt] + kb);
        }

#pragma unroll
        for (int p = 0; p < 4; p++) {
            // regs: r0=b0(nt=2p), r1=b1(2p), r2=b0(2p+1), r3=b1(2p+1)
            uint32_t h0, h1, h2, h3, l0, l1, l2, l3;
            ldsm_x4(h0, h1, h2, h3, bhi_b + offB[p] + kb);
            ldsm_x4(l0, l1, l2, l3, blo_b + offB[p] + kb);
#pragma unroll
            for (int mt = 0; mt < 2; mt++) {
                mma_bf16(acc[mt][2 * p], ah[mt][0], ah[mt][1], ah[mt][2],
                         ah[mt][3], h0, h1);
                mma_bf16(acc[mt][2 * p], ah[mt][0], ah[mt][1], ah[mt][2],
                         ah[mt][3], l0, l1);
                mma_bf16(acc[mt][2 * p], al[mt][0], al[mt][1], al[mt][2],
                         al[mt][3], h0, h1);
                mma_bf16(acc[mt][2 * p + 1], ah[mt][0], ah[mt][1], ah[mt][2],
                         ah[mt][3], h2, h3);
                mma_bf16(acc[mt][2 * p + 1], ah[mt][0], ah[mt][1], ah[mt][2],
                         ah[mt][3], l2, l3);
                mma_bf16(acc[mt][2 * p + 1], al[mt][0], al[mt][1], al[mt][2],
                         al[mt][3], h2, h3);
            }
        }
    }

    // Epilogue: d0,d1 -> (row + lane/4, col + (lane%3..)*2); d2,d3 -> row+8
    const float* bias_s = reinterpret_cast<const float*>(sm + SM_BIAS);
    const int r_in = lane >> 2;
    const int c_in = (lane & 3) * 2;
#pragma unroll
    for (int mt = 0; mt < 2; mt++) {
        int row_a = row0 + wr * 32 + mt * 16 + r_in;
        int row_b = row_a + 8;
#pragma unroll
        for (int nt = 0; nt < 8; nt++) {
            int cl = wc * 64 + nt * 8 + c_in;
            float bx = bias_s[cl], by = bias_s[cl + 1];
            if (row_a < n_rows) {
                float2 o = make_float2(acc[mt][nt][0] + bx,
                                       acc[mt][nt][1] + by);
                *reinterpret_cast<float2*>(C + (size_t)row_a * ldc + col0 + cl) = o;
            }
            if (row_b < n_rows) {
                float2 o = make_float2(acc[mt][nt][2] + bx,
                                       acc[mt][nt][3] + by);
                *reinterpret_cast<float2*>(C + (size_t)row_b * ldc + col0 + cl) = o;
            }
        }
    }
}

// ---------------------------------------------------------------------------
// Edge scatter: one warp per edge. messages[dst] += T[src] + b_msg
// ---------------------------------------------------------------------------
__global__ void scatter_kernel(const int* __restrict__ esrc,
                               const int* __restrict__ edst,
                               const float* __restrict__ b_msg, int n_edges) {
    int gwarp = (blockIdx.x * blockDim.x + threadIdx.x) >> 5;
    int lane  = threadIdx.x & 31;
    if (gwarp >= n_edges) return;
    int s = esrc[gwarp];
    int d = edst[gwarp];
    float4 v = reinterpret_cast<const float4*>(g_T + (size_t)s * DIM_H)[lane];
    float4 b = reinterpret_cast<const float4*>(b_msg)[lane];
    v.x += b.x; v.y += b.y; v.z += b.z; v.w += b.w;
    float* p = g_msg + (size_t)d * DIM_H + lane * 4;
    asm volatile("red.global.add.v4.f32 [%0], {%1, %2, %3, %4};"
                 :: "l"(p), "f"(v.x), "f"(v.y), "f"(v.z), "f"(v.w) : "memory");
}

// ---------------------------------------------------------------------------
// Fused GRU gates + LayerNorm + message residual. One warp per node.
// ---------------------------------------------------------------------------
__device__ __forceinline__ float sigmoidf_(float x) {
    return 1.0f / (1.0f + expf(-x));
}

__global__ void gru_ln_kernel(const float* __restrict__ nodes,
                              const float* __restrict__ gamma,
                              const float* __restrict__ beta,
                              float* __restrict__ out, int n_nodes) {
    int gwarp = (blockIdx.x * blockDim.x + threadIdx.x) >> 5;
    int lane  = threadIdx.x & 31;
    if (gwarp >= n_nodes) return;

    size_t base  = (size_t)gwarp * DIM_H;
    size_t gbase = (size_t)gwarp * DIM_3H;

    float4 h4  = reinterpret_cast<const float4*>(nodes + base)[lane];
    float4 m4  = reinterpret_cast<const float4*>(g_msg + base)[lane];
    float4 ir4 = reinterpret_cast<const float4*>(g_gi + gbase)[lane];
    float4 iz4 = reinterpret_cast<const float4*>(g_gi + gbase + 128)[lane];
    float4 in4 = reinterpret_cast<const float4*>(g_gi + gbase + 256)[lane];
    float4 hr4 = reinterpret_cast<const float4*>(g_gh + gbase)[lane];
    float4 hz4 = reinterpret_cast<const float4*>(g_gh + gbase + 128)[lane];
    float4 hn4 = reinterpret_cast<const float4*>(g_gh + gbase + 256)[lane];

    float hh[4] = {h4.x, h4.y, h4.z, h4.w};
    float ir[4] = {ir4.x, ir4.y, ir4.z, ir4.w};
    float iz[4] = {iz4.x, iz4.y, iz4.z, iz4.w};
    float in_[4]= {in4.x, in4.y, in4.z, in4.w};
    float hr[4] = {hr4.x, hr4.y, hr4.z, hr4.w};
    float hz[4] = {hz4.x, hz4.y, hz4.z, hz4.w};
    float hn[4] = {hn4.x, hn4.y, hn4.z, hn4.w};

    float hx[4];
    float s = 0.f, s2 = 0.f;
#pragma unroll
    for (int c = 0; c < 4; c++) {
        float r = sigmoidf_(ir[c] + hr[c]);
        float z = sigmoidf_(iz[c] + hz[c]);
        float n = tanhf(in_[c] + r * hn[c]);
        hx[c] = (1.0f - z) * n + z * hh[c];
        s  += hx[c];
        s2 += hx[c] * hx[c];
    }
#pragma unroll
    for (int off = 16; off > 0; off >>= 1) {
        s  += __shfl_xor_sync(0xFFFFFFFF, s,  off);
        s2 += __shfl_xor_sync(0xFFFFFFFF, s2, off);
    }
    float mu   = s  * (1.0f / DIM_H);
    float var  = s2 * (1.0f / DIM_H) - mu * mu;
    float rstd = rsqrtf(var + LN_EPS);

    float4 g4 = reinterpret_cast<const float4*>(gamma)[lane];
    float4 b4 = reinterpret_cast<const float4*>(beta)[lane];
    float gg[4] = {g4.x, g4.y, g4.z, g4.w};
    float bb[4] = {b4.x, b4.y, b4.z, b4.w};
    float mm[4] = {m4.x, m4.y, m4.z, m4.w};

    float o[4];
#pragma unroll
    for (int c = 0; c < 4; c++)
        o[c] = gg[c] * (hx[c] - mu) * rstd + bb[c] + mm[c];

    reinterpret_cast<float4*>(out + base)[lane] =
        make_float4(o[0], o[1], o[2], o[3]);
}

// ---------------------------------------------------------------------------
// Launch
// ---------------------------------------------------------------------------
extern "C" void kernel_launch(void* const* d_in, const int* in_sizes, int n_in,
                              void* d_out, int out_size) {
    const float* nodes = (const float*)d_in[0];
    const float* W_msg = (const float*)d_in[1];
    const float* b_msg = (const float*)d_in[2];
    const float* w_ih  = (const float*)d_in[3];
    const float* w_hh  = (const float*)d_in[4];
    const float* b_ih  = (const float*)d_in[5];
    const float* b_hh  = (const float*)d_in[6];
    const float* gamma = (const float*)d_in[7];
    const float* beta  = (const float*)d_in[8];
    const int*   esrc  = (const int*)d_in[9];
    const int*   edst  = (const int*)d_in[10];
    float* out = (float*)d_out;

    int n_nodes = in_sizes[0] / DIM_H;
    int n_edges = in_sizes[9];

    float *pT, *pMsg, *pGi, *pGh, *pBias2;
    __nv_bfloat16 *pWmH, *pWmL, *pWihH, *pWihL, *pWhhH, *pWhhL;
    cudaGetSymbolAddress((void**)&pT,     g_T);
    cudaGetSymbolAddress((void**)&pMsg,   g_msg);
    cudaGetSymbolAddress((void**)&pGi,    g_gi);
    cudaGetSymbolAddress((void**)&pGh,    g_gh);
    cudaGetSymbolAddress((void**)&pBias2, g_bias2);
    cudaGetSymbolAddress((void**)&pWmH,  g_Wm_hi);
    cudaGetSymbolAddress((void**)&pWmL,  g_Wm_lo);
    cudaGetSymbolAddress((void**)&pWihH, g_Wih_hi);
    cudaGetSymbolAddress((void**)&pWihL, g_Wih_lo);
    cudaGetSymbolAddress((void**)&pWhhH, g_Whh_hi);
    cudaGetSymbolAddress((void**)&pWhhL, g_Whh_lo);

    cudaFuncSetAttribute(gemm_tc_kernel,
                         cudaFuncAttributeMaxDynamicSharedMemorySize, SM_TOTAL);

    int rt = (n_nodes + 127) / 128;  // 128-row tiles

    zero_kernel<<<(n_nodes * 32 + 255) / 256, 256>>>(n_nodes);
    colsum_kernel<<<256, 256>>>(nodes, n_nodes);

    split_kernel<<<(DIM_H * DIM_H + 255) / 256, 256>>>(W_msg, pWmH, pWmL,
                                                       DIM_H * DIM_H);
    split_kernel<<<(DIM_3H * DIM_H + 255) / 256, 256>>>(w_ih, pWihH, pWihL,
                                                        DIM_3H * DIM_H);
    split_kernel<<<(DIM_3H * DIM_H + 255) / 256, 256>>>(w_hh, pWhhH, pWhhL,
                                                        DIM_3H * DIM_H);

    // T = nodes @ W_msg^T  (b_msg added per-edge in scatter)
    gemm_tc_kernel<<<dim3(rt, 1), 256, SM_TOTAL>>>(nodes, pWmH, pWmL, nullptr,
                                                   pT, n_nodes, DIM_H);
    // messages[dst] += T[src] + b_msg
    scatter_kernel<<<(n_edges + 7) / 8, 256>>>(esrc, edst, b_msg, n_edges);

    // bias2 = b_ih + w_ih @ mean(nodes)
    bias2_kernel<<<1, DIM_3H>>>(w_ih, b_ih, n_nodes);

    // gi = messages @ w_ih^T + bias2 ; gh = nodes @ w_hh^T + b_hh
    gemm_tc_kernel<<<dim3(rt, 3), 256, SM_TOTAL>>>(pMsg, pWihH, pWihL, pBias2,
                                                   pGi, n_nodes, DIM_3H);
    gemm_tc_kernel<<<dim3(rt, 3), 256, SM_TOTAL>>>(nodes, pWhhH, pWhhL, b_hh,
                                                   pGh, n_nodes, DIM_3H);

    // GRU gates + LayerNorm + message residual
    gru_ln_kernel<<<(n_nodes + 7) / 8, 256>>>(nodes, gamma, beta, out, n_nodes);
}

// round 4
// speedup vs baseline: 1.9579x; 1.3041x over previous
#include <cuda_runtime.h>
#include <cuda_bf16.h>
#include <math.h>
#include <stdint.h>

#define DIM_H  128
#define DIM_3H 384
#define MAX_N  50000
#define MAX_E  600000
#define LN_EPS 1e-5f

// ---------------------------------------------------------------------------
// Scratch (device globals: allocation-free per harness rules)
// ---------------------------------------------------------------------------
__device__ float g_TG[MAX_N * 512];         // [T(128) | gh(384)] per node
__device__ float g_msg[MAX_N * DIM_H];      // segment-summed messages
__device__ float g_gi[MAX_N * DIM_3H];      // msg @ w_ih^T + bias2
__device__ float g_colsum[DIM_H];
__device__ float g_bias2[DIM_3H];           // b_ih + w_ih @ mean(nodes)
__device__ float g_biasA[512];              // [0(128) | b_hh(384)]

// bf16 hi/lo splits
__device__ __nv_bfloat16 g_nhi[MAX_N * DIM_H];   // nodes hi
__device__ __nv_bfloat16 g_nlo[MAX_N * DIM_H];   // nodes lo
__device__ __nv_bfloat16 g_mhi[MAX_N * DIM_H];   // msg hi
__device__ __nv_bfloat16 g_mlo[MAX_N * DIM_H];   // msg lo
__device__ __nv_bfloat16 g_WcatH[512 * DIM_H];   // [W_msg; w_hh] hi
__device__ __nv_bfloat16 g_WcatL[512 * DIM_H];   // [W_msg; w_hh] lo
__device__ __nv_bfloat16 g_WihH[DIM_3H * DIM_H];
__device__ __nv_bfloat16 g_WihL[DIM_3H * DIM_H];

// ---------------------------------------------------------------------------
// PTX helpers (arch-neutral sm_80+: ldmatrix / mma.sync / cp.async)
// ---------------------------------------------------------------------------
__device__ __forceinline__ uint32_t smem_u32(const void* p) {
    uint32_t a;
    asm("{ .reg .u64 t; cvta.to.shared.u64 t, %1; cvt.u32.u64 %0, t; }"
        : "=r"(a) : "l"(p));
    return a;
}

__device__ __forceinline__ void ldsm_x4(uint32_t& r0, uint32_t& r1,
                                        uint32_t& r2, uint32_t& r3,
                                        uint32_t addr) {
    asm volatile("ldmatrix.sync.aligned.m8n8.x4.shared.b16 {%0,%1,%2,%3}, [%4];"
                 : "=r"(r0), "=r"(r1), "=r"(r2), "=r"(r3) : "r"(addr));
}

__device__ __forceinline__ void mma_bf16(float* d, uint32_t a0, uint32_t a1,
                                         uint32_t a2, uint32_t a3,
                                         uint32_t b0, uint32_t b1) {
    asm volatile(
        "mma.sync.aligned.m16n8k16.row.col.f32.bf16.bf16.f32 "
        "{%0,%1,%2,%3}, {%4,%5,%6,%7}, {%8,%9}, {%0,%1,%2,%3};"
        : "+f"(d[0]), "+f"(d[1]), "+f"(d[2]), "+f"(d[3])
        : "r"(a0), "r"(a1), "r"(a2), "r"(a3), "r"(b0), "r"(b1));
}

#define CP_ASYNC16(dst, src, sz)                                               \
    asm volatile("cp.async.cg.shared.global [%0], [%1], 16, %2;"               \
                 :: "r"(dst), "l"(src), "r"(sz) : "memory")
#define CP_COMMIT() asm volatile("cp.async.commit_group;" ::: "memory")
#define CP_WAIT0()  asm volatile("cp.async.wait_group 0;" ::: "memory")
#define CP_WAIT1()  asm volatile("cp.async.wait_group 1;" ::: "memory")

// ---------------------------------------------------------------------------
// Small kernels
// ---------------------------------------------------------------------------
__global__ void zero_kernel(int n_nodes) {
    int i = blockIdx.x * blockDim.x + threadIdx.x;
    float4 z = make_float4(0.f, 0.f, 0.f, 0.f);
    int total = n_nodes * (DIM_H / 4);
    if (i < total) reinterpret_cast<float4*>(g_msg)[i] = z;
    if (i < DIM_H / 4) reinterpret_cast<float4*>(g_colsum)[i] = z;
}

__global__ void colsum_kernel(const float* __restrict__ nodes, int n_nodes) {
    __shared__ float sh[256];
    int dim = threadIdx.x & 127;
    int sub = threadIdx.x >> 7;
    float acc = 0.f;
    for (int r = blockIdx.x * 2 + sub; r < n_nodes; r += gridDim.x * 2)
        acc += nodes[(size_t)r * DIM_H + dim];
    sh[threadIdx.x] = acc;
    __syncthreads();
    if (sub == 0) atomicAdd(&g_colsum[dim], sh[dim] + sh[dim + 128]);
}

__global__ void bias2_kernel(const float* __restrict__ w_ih,
                             const float* __restrict__ b_ih, int n_nodes) {
    __shared__ float mean_s[DIM_H];
    int tid = threadIdx.x;  // 384 threads
    if (tid < DIM_H) mean_s[tid] = g_colsum[tid] * (1.0f / (float)n_nodes);
    __syncthreads();
    float acc = b_ih[tid];
#pragma unroll 8
    for (int k = 0; k < DIM_H; k++)
        acc = fmaf(w_ih[(size_t)tid * DIM_H + k], mean_s[k], acc);
    g_bias2[tid] = acc;
}

__global__ void biasA_kernel(const float* __restrict__ b_hh) {
    int tid = threadIdx.x;  // 512
    g_biasA[tid] = (tid < 128) ? 0.f : b_hh[tid - 128];
}

// Split fp32 -> bf16 hi/lo (weights, row count arbitrary)
__global__ void split_kernel(const float* __restrict__ src,
                             __nv_bfloat16* __restrict__ hi,
                             __nv_bfloat16* __restrict__ lo, int n) {
    int i = blockIdx.x * blockDim.x + threadIdx.x;
    if (i >= n) return;
    float x = src[i];
    __nv_bfloat16 h = __float2bfloat16(x);
    hi[i] = h;
    lo[i] = __float2bfloat16(x - __bfloat162float(h));
}

// Vectorized activation split: 8 elems/thread, packed 16B writes
__global__ void convert_kernel(const float* __restrict__ src,
                               __nv_bfloat16* __restrict__ hi,
                               __nv_bfloat16* __restrict__ lo, int n8) {
    int i = blockIdx.x * blockDim.x + threadIdx.x;
    if (i >= n8) return;
    float4 v0 = reinterpret_cast<const float4*>(src)[i * 2];
    float4 v1 = reinterpret_cast<const float4*>(src)[i * 2 + 1];
    float xs[8] = {v0.x, v0.y, v0.z, v0.w, v1.x, v1.y, v1.z, v1.w};
    uint32_t hb[8], lb[8];
#pragma unroll
    for (int t = 0; t < 8; t++) {
        __nv_bfloat16 h = __float2bfloat16(xs[t]);
        __nv_bfloat16 l = __float2bfloat16(xs[t] - __bfloat162float(h));
        hb[t] = (uint32_t)__bfloat16_as_ushort(h);
        lb[t] = (uint32_t)__bfloat16_as_ushort(l);
    }
    uint4 ph = make_uint4(hb[0] | (hb[1] << 16), hb[2] | (hb[3] << 16),
                          hb[4] | (hb[5] << 16), hb[6] | (hb[7] << 16));
    uint4 pl = make_uint4(lb[0] | (lb[1] << 16), lb[2] | (lb[3] << 16),
                          lb[4] | (lb[5] << 16), lb[6] | (lb[7] << 16));
    reinterpret_cast<uint4*>(hi)[i] = ph;
    reinterpret_cast<uint4*>(lo)[i] = pl;
}

// ---------------------------------------------------------------------------
// Pipelined tensor-core GEMM: C[128 rows, n_ct*128 cols] = A @ B^T + bias
// All-bf16 inputs (pre-split hi/lo). A resident; B double-buffered cp.async.
// 512 threads, warp tile 16x64, split 3-product fp32 accumulation.
// ---------------------------------------------------------------------------
#define LDA 136
#define TILE_B (128 * LDA * 2)        // 34816 B
#define SM_AHI  0
#define SM_ALO  TILE_B
#define SM_B    (2 * TILE_B)          // 4 buffers: (buf*2 + hi/lo)*TILE_B
#define SM_BIAS (6 * TILE_B)          // up to 512 floats
#define SM_TOTAL (SM_BIAS + 2048)

// Copy a 128x128 bf16 tile (global row-major, ld=128) into smem (LDA=136)
__device__ __forceinline__ void cp_tile(uint32_t sdst,
                                        const __nv_bfloat16* gsrc,
                                        int rows_valid) {
    int tid = threadIdx.x;
#pragma unroll
    for (int i = 0; i < 4; i++) {
        int idx = tid + i * 512;          // 2048 chunks of 16B
        int r = idx >> 4, c = idx & 15;
        uint32_t d = sdst + (uint32_t)(r * LDA + c * 8) * 2;
        int ok = (r < rows_valid);
        const __nv_bfloat16* s = gsrc + (size_t)(ok ? r : 0) * DIM_H + c * 8;
        CP_ASYNC16(d, s, ok ? 16 : 0);
    }
}

__global__ void __launch_bounds__(512, 1)
gemm_tc2(const __nv_bfloat16* __restrict__ Ahi,
         const __nv_bfloat16* __restrict__ Alo,
         const __nv_bfloat16* __restrict__ Bhi,
         const __nv_bfloat16* __restrict__ Blo,
         const float* __restrict__ bias,
         float* __restrict__ C,
         int n_rows, int n_ct, int ldc) {
    extern __shared__ char sm[];
    uint32_t smb = smem_u32(sm);
    const int tid = threadIdx.x;
    const int wid = tid >> 5;
    const int lane = tid & 31;
    const int row0 = blockIdx.x * 128;
    const int rows_valid = n_rows - row0;

    // Prologue: A (hi+lo) + B tile 0; prefetch B tile 1
    cp_tile(smb + SM_AHI, Ahi + (size_t)row0 * DIM_H, rows_valid);
    cp_tile(smb + SM_ALO, Alo + (size_t)row0 * DIM_H, rows_valid);
    cp_tile(smb + SM_B, Bhi, 128);
    cp_tile(smb + SM_B + TILE_B, Blo, 128);
    CP_COMMIT();
    if (n_ct > 1) {
        cp_tile(smb + SM_B + 2 * TILE_B, Bhi + 128 * DIM_H, 128);
        cp_tile(smb + SM_B + 3 * TILE_B, Blo + 128 * DIM_H, 128);
        CP_COMMIT();
    }
    float* bias_s = reinterpret_cast<float*>(sm + SM_BIAS);
    for (int i = tid; i < n_ct * 128; i += 512)
        bias_s[i] = bias ? bias[i] : 0.f;
    if (n_ct > 1) CP_WAIT1(); else CP_WAIT0();
    __syncthreads();

    // Warp tiling: 16 warps; wr (0..7) = 16-row group, wc (0..1) = 64-col group
    const int wr = wid & 7;
    const int wc = wid >> 3;

    const int a_m = lane & 15;
    const int a_k = (lane >> 4) * 8;
    const uint32_t offA = (uint32_t)(((wr * 16 + a_m) * LDA + a_k) * 2);

    const int b_n = (lane & 7) + (lane >> 4) * 8;
    const int b_k = ((lane >> 3) & 1) * 8;
    uint32_t offB[4];
#pragma unroll
    for (int p = 0; p < 4; p++)
        offB[p] = (uint32_t)(((wc * 64 + p * 16 + b_n) * LDA + b_k) * 2);

    const int r_in = lane >> 2;
    const int c_in = (lane & 3) * 2;
    const int row_a = row0 + wr * 16 + r_in;
    const int row_b = row_a + 8;

    for (int ct = 0; ct < n_ct; ct++) {
        const uint32_t bhi_b = smb + SM_B + (uint32_t)(ct & 1) * 2 * TILE_B;
        const uint32_t blo_b = bhi_b + TILE_B;

        float acc[8][4];
#pragma unroll
        for (int nt = 0; nt < 8; nt++)
#pragma unroll
            for (int e = 0; e < 4; e++) acc[nt][e] = 0.f;

#pragma unroll
        for (int ks = 0; ks < 8; ks++) {
            const uint32_t kb = ks * 32;
            uint32_t ah0, ah1, ah2, ah3, al0, al1, al2, al3;
            ldsm_x4(ah0, ah1, ah2, ah3, smb + SM_AHI + offA + kb);
            ldsm_x4(al0, al1, al2, al3, smb + SM_ALO + offA + kb);
#pragma unroll
            for (int p = 0; p < 4; p++) {
                uint32_t h0, h1, h2, h3, l0, l1, l2, l3;
                ldsm_x4(h0, h1, h2, h3, bhi_b + offB[p] + kb);
                ldsm_x4(l0, l1, l2, l3, blo_b + offB[p] + kb);
                mma_bf16(acc[2 * p],     ah0, ah1, ah2, ah3, h0, h1);
                mma_bf16(acc[2 * p],     al0, al1, al2, al3, h0, h1);
                mma_bf16(acc[2 * p],     ah0, ah1, ah2, ah3, l0, l1);
                mma_bf16(acc[2 * p + 1], ah0, ah1, ah2, ah3, h2, h3);
                mma_bf16(acc[2 * p + 1], al0, al1, al2, al3, h2, h3);
                mma_bf16(acc[2 * p + 1], ah0, ah1, ah2, ah3, l2, l3);
            }
        }

        // Epilogue for this col tile
        const int colbase = ct * 128 + wc * 64;
#pragma unroll
        for (int nt = 0; nt < 8; nt++) {
            int cl = colbase + nt * 8 + c_in;
            float bx = bias_s[cl], by = bias_s[cl + 1];
            if (row_a < n_rows)
                *reinterpret_cast<float2*>(C + (size_t)row_a * ldc + cl) =
                    make_float2(acc[nt][0] + bx, acc[nt][1] + by);
            if (row_b < n_rows)
                *reinterpret_cast<float2*>(C + (size_t)row_b * ldc + cl) =
                    make_float2(acc[nt][2] + bx, acc[nt][3] + by);
        }

        // Prefetch B tile ct+2 into the buffer we just finished
        if (ct + 1 < n_ct) {
            __syncthreads();
            bool pf = (ct + 2) < n_ct;
            if (pf) {
                uint32_t dst = smb + SM_B + (uint32_t)(ct & 1) * 2 * TILE_B;
                cp_tile(dst, Bhi + (size_t)(ct + 2) * 128 * DIM_H, 128);
                cp_tile(dst + TILE_B, Blo + (size_t)(ct + 2) * 128 * DIM_H, 128);
                CP_COMMIT();
                CP_WAIT1();
            } else {
                CP_WAIT0();
            }
            __syncthreads();
        }
    }
}

// ---------------------------------------------------------------------------
// Edge scatter: one warp per edge. messages[dst] += T[src] + b_msg
// T lives in g_TG cols 0..127, row stride 512.
// ---------------------------------------------------------------------------
__global__ void scatter_kernel(const int* __restrict__ esrc,
                               const int* __restrict__ edst,
                               const float* __restrict__ b_msg, int n_edges) {
    int gwarp = (blockIdx.x * blockDim.x + threadIdx.x) >> 5;
    int lane  = threadIdx.x & 31;
    if (gwarp >= n_edges) return;
    int s = esrc[gwarp];
    int d = edst[gwarp];
    float4 v = reinterpret_cast<const float4*>(g_TG + (size_t)s * 512)[lane];
    float4 b = reinterpret_cast<const float4*>(b_msg)[lane];
    v.x += b.x; v.y += b.y; v.z += b.z; v.w += b.w;
    float* p = g_msg + (size_t)d * DIM_H + lane * 4;
    asm volatile("red.global.add.v4.f32 [%0], {%1, %2, %3, %4};"
                 :: "l"(p), "f"(v.x), "f"(v.y), "f"(v.z), "f"(v.w) : "memory");
}

// ---------------------------------------------------------------------------
// Fused GRU gates + LayerNorm + message residual. One warp per node.
// gh = g_TG cols 128..511 (stride 512); gi = g_gi (stride 384).
// ---------------------------------------------------------------------------
__device__ __forceinline__ float sigmoidf_(float x) {
    return 1.0f / (1.0f + expf(-x));
}

__global__ void gru_ln_kernel(const float* __restrict__ nodes,
                              const float* __restrict__ gamma,
                              const float* __restrict__ beta,
                              float* __restrict__ out, int n_nodes) {
    int gwarp = (blockIdx.x * blockDim.x + threadIdx.x) >> 5;
    int lane  = threadIdx.x & 31;
    if (gwarp >= n_nodes) return;

    size_t base  = (size_t)gwarp * DIM_H;
    size_t gib   = (size_t)gwarp * DIM_3H;
    size_t ghb   = (size_t)gwarp * 512 + 128;

    float4 h4  = reinterpret_cast<const float4*>(nodes + base)[lane];
    float4 m4  = reinterpret_cast<const float4*>(g_msg + base)[lane];
    float4 ir4 = reinterpret_cast<const float4*>(g_gi + gib)[lane];
    float4 iz4 = reinterpret_cast<const float4*>(g_gi + gib + 128)[lane];
    float4 in4 = reinterpret_cast<const float4*>(g_gi + gib + 256)[lane];
    float4 hr4 = reinterpret_cast<const float4*>(g_TG + ghb)[lane];
    float4 hz4 = reinterpret_cast<const float4*>(g_TG + ghb + 128)[lane];
    float4 hn4 = reinterpret_cast<const float4*>(g_TG + ghb + 256)[lane];

    float hh[4] = {h4.x, h4.y, h4.z, h4.w};
    float ir[4] = {ir4.x, ir4.y, ir4.z, ir4.w};
    float iz[4] = {iz4.x, iz4.y, iz4.z, iz4.w};
    float in_[4]= {in4.x, in4.y, in4.z, in4.w};
    float hr[4] = {hr4.x, hr4.y, hr4.z, hr4.w};
    float hz[4] = {hz4.x, hz4.y, hz4.z, hz4.w};
    float hn[4] = {hn4.x, hn4.y, hn4.z, hn4.w};

    float hx[4];
    float s = 0.f, s2 = 0.f;
#pragma unroll
    for (int c = 0; c < 4; c++) {
        float r = sigmoidf_(ir[c] + hr[c]);
        float z = sigmoidf_(iz[c] + hz[c]);
        float n = tanhf(in_[c] + r * hn[c]);
        hx[c] = (1.0f - z) * n + z * hh[c];
        s  += hx[c];
        s2 += hx[c] * hx[c];
    }
#pragma unroll
    for (int off = 16; off > 0; off >>= 1) {
        s  += __shfl_xor_sync(0xFFFFFFFF, s,  off);
        s2 += __shfl_xor_sync(0xFFFFFFFF, s2, off);
    }
    float mu   = s  * (1.0f / DIM_H);
    float var  = s2 * (1.0f / DIM_H) - mu * mu;
    float rstd = rsqrtf(var + LN_EPS);

    float4 g4 = reinterpret_cast<const float4*>(gamma)[lane];
    float4 b4 = reinterpret_cast<const float4*>(beta)[lane];
    float gg[4] = {g4.x, g4.y, g4.z, g4.w};
    float bb[4] = {b4.x, b4.y, b4.z, b4.w};
    float mm[4] = {m4.x, m4.y, m4.z, m4.w};

    float o[4];
#pragma unroll
    for (int c = 0; c < 4; c++)
        o[c] = gg[c] * (hx[c] - mu) * rstd + bb[c] + mm[c];

    reinterpret_cast<float4*>(out + base)[lane] =
        make_float4(o[0], o[1], o[2], o[3]);
}

// ---------------------------------------------------------------------------
// Launch
// ---------------------------------------------------------------------------
extern "C" void kernel_launch(void* const* d_in, const int* in_sizes, int n_in,
                              void* d_out, int out_size) {
    const float* nodes = (const float*)d_in[0];
    const float* W_msg = (const float*)d_in[1];
    const float* b_msg = (const float*)d_in[2];
    const float* w_ih  = (const float*)d_in[3];
    const float* w_hh  = (const float*)d_in[4];
    const float* b_ih  = (const float*)d_in[5];
    const float* b_hh  = (const float*)d_in[6];
    const float* gamma = (const float*)d_in[7];
    const float* beta  = (const float*)d_in[8];
    const int*   esrc  = (const int*)d_in[9];
    const int*   edst  = (const int*)d_in[10];
    float* out = (float*)d_out;

    int n_nodes = in_sizes[0] / DIM_H;
    int n_edges = in_sizes[9];

    float *pTG, *pMsg, *pGi, *pBias2, *pBiasA;
    __nv_bfloat16 *pNH, *pNL, *pMH, *pML, *pWcH, *pWcL, *pWiH, *pWiL;
    cudaGetSymbolAddress((void**)&pTG,    g_TG);
    cudaGetSymbolAddress((void**)&pMsg,   g_msg);
    cudaGetSymbolAddress((void**)&pGi,    g_gi);
    cudaGetSymbolAddress((void**)&pBias2, g_bias2);
    cudaGetSymbolAddress((void**)&pBiasA, g_biasA);
    cudaGetSymbolAddress((void**)&pNH, g_nhi);
    cudaGetSymbolAddress((void**)&pNL, g_nlo);
    cudaGetSymbolAddress((void**)&pMH, g_mhi);
    cudaGetSymbolAddress((void**)&pML, g_mlo);
    cudaGetSymbolAddress((void**)&pWcH, g_WcatH);
    cudaGetSymbolAddress((void**)&pWcL, g_WcatL);
    cudaGetSymbolAddress((void**)&pWiH, g_WihH);
    cudaGetSymbolAddress((void**)&pWiL, g_WihL);

    cudaFuncSetAttribute(gemm_tc2,
                         cudaFuncAttributeMaxDynamicSharedMemorySize, SM_TOTAL);

    int rt = (n_nodes + 127) / 128;
    int n8 = n_nodes * DIM_H / 8;

    zero_kernel<<<(n_nodes * 32 + 255) / 256, 256>>>(n_nodes);
    colsum_kernel<<<256, 256>>>(nodes, n_nodes);

    // Weight prep: Wcat = [W_msg; w_hh] split; w_ih split; biasA
    split_kernel<<<(DIM_H * DIM_H + 255) / 256, 256>>>(W_msg, pWcH, pWcL,
                                                       DIM_H * DIM_H);
    split_kernel<<<(DIM_3H * DIM_H + 255) / 256, 256>>>(
        w_hh, pWcH + 128 * DIM_H, pWcL + 128 * DIM_H, DIM_3H * DIM_H);
    split_kernel<<<(DIM_3H * DIM_H + 255) / 256, 256>>>(w_ih, pWiH, pWiL,
                                                        DIM_3H * DIM_H);
    biasA_kernel<<<1, 512>>>(b_hh);

    // Activation split: nodes -> hi/lo
    convert_kernel<<<(n8 + 255) / 256, 256>>>(nodes, pNH, pNL, n8);

    // [T | gh] = nodes @ [W_msg; w_hh]^T + [0; b_hh]
    gemm_tc2<<<rt, 512, SM_TOTAL>>>(pNH, pNL, pWcH, pWcL, pBiasA, pTG,
                                    n_nodes, 4, 512);

    // messages[dst] += T[src] + b_msg
    scatter_kernel<<<(n_edges + 7) / 8, 256>>>(esrc, edst, b_msg, n_edges);

    // bias2 = b_ih + w_ih @ mean(nodes)
    bias2_kernel<<<1, DIM_3H>>>(w_ih, b_ih, n_nodes);

    // msg -> hi/lo, then gi = msg @ w_ih^T + bias2
    convert_kernel<<<(n8 + 255) / 256, 256>>>(pMsg, pMH, pML, n8);
    gemm_tc2<<<rt, 512, SM_TOTAL>>>(pMH, pML, pWiH, pWiL, pBias2, pGi,
                                    n_nodes, 3, DIM_3H);

    // GRU gates + LayerNorm + message residual
    gru_ln_kernel<<<(n_nodes + 7) / 8, 256>>>(nodes, gamma, beta, out, n_nodes);
}

// round 5
// speedup vs baseline: 2.2251x; 1.1364x over previous
#include <cuda_runtime.h>
#include <cuda_fp16.h>
#include <math.h>
#include <stdint.h>

#define DIM_H  128
#define DIM_3H 384
#define MAX_N  50000
#define MAX_E  600000
#define LN_EPS 1e-5f

// ---------------------------------------------------------------------------
// Scratch (device globals: allocation-free per harness rules)
// ---------------------------------------------------------------------------
__device__ float g_T[MAX_N * DIM_H];        // nodes @ W_msg^T (dense rows)
__device__ float g_gh[MAX_N * DIM_3H];      // nodes @ w_hh^T + b_hh
__device__ float g_msg[MAX_N * DIM_H];      // segment-summed messages
__device__ float g_gi[MAX_N * DIM_3H];      // msg @ w_ih^T + bias2
__device__ float g_colsum[DIM_H];
__device__ float g_bias2[DIM_3H];           // b_ih + w_ih @ mean(nodes)

// fp16 operands
__device__ __half g_nhi[MAX_N * DIM_H];     // nodes hi
__device__ __half g_nlo[MAX_N * DIM_H];     // nodes lo (residual)
__device__ __half g_mhi[MAX_N * DIM_H];     // msg hi
__device__ __half g_mlo[MAX_N * DIM_H];     // msg lo
__device__ __half g_Wcat[512 * DIM_H];      // [W_msg; w_hh] fp16
__device__ __half g_Wih[DIM_3H * DIM_H];    // w_ih fp16

// ---------------------------------------------------------------------------
// PTX helpers (arch-neutral sm_80+: ldmatrix / mma.sync / cp.async)
// ---------------------------------------------------------------------------
__device__ __forceinline__ uint32_t smem_u32(const void* p) {
    uint32_t a;
    asm("{ .reg .u64 t; cvta.to.shared.u64 t, %1; cvt.u32.u64 %0, t; }"
        : "=r"(a) : "l"(p));
    return a;
}

__device__ __forceinline__ void ldsm_x4(uint32_t& r0, uint32_t& r1,
                                        uint32_t& r2, uint32_t& r3,
                                        uint32_t addr) {
    asm volatile("ldmatrix.sync.aligned.m8n8.x4.shared.b16 {%0,%1,%2,%3}, [%4];"
                 : "=r"(r0), "=r"(r1), "=r"(r2), "=r"(r3) : "r"(addr));
}

__device__ __forceinline__ void mma_f16(float* d, uint32_t a0, uint32_t a1,
                                        uint32_t a2, uint32_t a3,
                                        uint32_t b0, uint32_t b1) {
    asm volatile(
        "mma.sync.aligned.m16n8k16.row.col.f32.f16.f16.f32 "
        "{%0,%1,%2,%3}, {%4,%5,%6,%7}, {%8,%9}, {%0,%1,%2,%3};"
        : "+f"(d[0]), "+f"(d[1]), "+f"(d[2]), "+f"(d[3])
        : "r"(a0), "r"(a1), "r"(a2), "r"(a3), "r"(b0), "r"(b1));
}

#define CP_ASYNC16(dst, src, sz)                                               \
    asm volatile("cp.async.cg.shared.global [%0], [%1], 16, %2;"               \
                 :: "r"(dst), "l"(src), "r"(sz) : "memory")
#define CP_COMMIT() asm volatile("cp.async.commit_group;" ::: "memory")
#define CP_WAIT0()  asm volatile("cp.async.wait_group 0;" ::: "memory")
#define CP_WAIT1()  asm volatile("cp.async.wait_group 1;" ::: "memory")

// ---------------------------------------------------------------------------
// Small kernels
// ---------------------------------------------------------------------------
__global__ void zero_kernel(int n_nodes) {
    int i = blockIdx.x * blockDim.x + threadIdx.x;
    float4 z = make_float4(0.f, 0.f, 0.f, 0.f);
    int total = n_nodes * (DIM_H / 4);
    if (i < total) reinterpret_cast<float4*>(g_msg)[i] = z;
    if (i < DIM_H / 4) reinterpret_cast<float4*>(g_colsum)[i] = z;
}

// fp32 -> fp16 (weights)
__global__ void convW_kernel(const float* __restrict__ src,
                             __half* __restrict__ dst, int n8) {
    int i = blockIdx.x * blockDim.x + threadIdx.x;
    if (i >= n8) return;
    float4 v0 = reinterpret_cast<const float4*>(src)[i * 2];
    float4 v1 = reinterpret_cast<const float4*>(src)[i * 2 + 1];
    float xs[8] = {v0.x, v0.y, v0.z, v0.w, v1.x, v1.y, v1.z, v1.w};
    uint32_t hb[8];
#pragma unroll
    for (int t = 0; t < 8; t++)
        hb[t] = (uint32_t)__half_as_ushort(__float2half_rn(xs[t]));
    reinterpret_cast<uint4*>(dst)[i] =
        make_uint4(hb[0] | (hb[1] << 16), hb[2] | (hb[3] << 16),
                   hb[4] | (hb[5] << 16), hb[6] | (hb[7] << 16));
}

// fp32 -> fp16 hi/lo split; optional per-column sum accumulation (layout
// assumed row-major with 128 cols; thread i handles cols (i%16)*8..+7)
__global__ void convertA_kernel(const float* __restrict__ src,
                                __half* __restrict__ hi,
                                __half* __restrict__ lo,
                                int n8, int do_colsum) {
    __shared__ float cs[DIM_H];
    int tid = threadIdx.x;
    if (do_colsum) {
        if (tid < DIM_H) cs[tid] = 0.f;
        __syncthreads();
    }
    int i = blockIdx.x * blockDim.x + tid;
    if (i < n8) {
        float4 v0 = reinterpret_cast<const float4*>(src)[i * 2];
        float4 v1 = reinterpret_cast<const float4*>(src)[i * 2 + 1];
        float xs[8] = {v0.x, v0.y, v0.z, v0.w, v1.x, v1.y, v1.z, v1.w};
        uint32_t hb[8], lb[8];
#pragma unroll
        for (int t = 0; t < 8; t++) {
            __half h = __float2half_rn(xs[t]);
            __half l = __float2half_rn(xs[t] - __half2float(h));
            hb[t] = (uint32_t)__half_as_ushort(h);
            lb[t] = (uint32_t)__half_as_ushort(l);
        }
        reinterpret_cast<uint4*>(hi)[i] =
            make_uint4(hb[0] | (hb[1] << 16), hb[2] | (hb[3] << 16),
                       hb[4] | (hb[5] << 16), hb[6] | (hb[7] << 16));
        reinterpret_cast<uint4*>(lo)[i] =
            make_uint4(lb[0] | (lb[1] << 16), lb[2] | (lb[3] << 16),
                       lb[4] | (lb[5] << 16), lb[6] | (lb[7] << 16));
        if (do_colsum) {
            int c0 = (i & 15) * 8;
#pragma unroll
            for (int t = 0; t < 8; t++) atomicAdd(&cs[c0 + t], xs[t]);
        }
    }
    if (do_colsum) {
        __syncthreads();
        if (tid < DIM_H) atomicAdd(&g_colsum[tid], cs[tid]);
    }
}

__global__ void bias2_kernel(const float* __restrict__ w_ih,
                             const float* __restrict__ b_ih, int n_nodes) {
    __shared__ float mean_s[DIM_H];
    int tid = threadIdx.x;  // 384 threads
    if (tid < DIM_H) mean_s[tid] = g_colsum[tid] * (1.0f / (float)n_nodes);
    __syncthreads();
    float acc = b_ih[tid];
#pragma unroll 8
    for (int k = 0; k < DIM_H; k++)
        acc = fmaf(w_ih[(size_t)tid * DIM_H + k], mean_s[k], acc);
    g_bias2[tid] = acc;
}

// ---------------------------------------------------------------------------
// Pipelined tensor-core GEMM: rows tile = 128, cols = n_ct*128.
// A split fp16 (hi resident + lo resident); B plain fp16 double-buffered.
// D = Ahi@B^T + Alo@B^T (fp32 accum). ct0 -> C0/ldc0, ct>=1 -> C1/ldc1.
// ---------------------------------------------------------------------------
#define LDA 136
#define TILE_B (128 * LDA * 2)        // 34816 B per fp16 tile
#define SM_AHI  0
#define SM_ALO  TILE_B
#define SM_B    (2 * TILE_B)          // two B buffers
#define SM_BIAS (4 * TILE_B)
#define SM_TOTAL (SM_BIAS + 2048)

__device__ __forceinline__ void cp_tile(uint32_t sdst, const __half* gsrc,
                                        int rows_valid) {
    int tid = threadIdx.x;
#pragma unroll
    for (int i = 0; i < 4; i++) {
        int idx = tid + i * 512;          // 2048 chunks of 16B
        int r = idx >> 4, c = idx & 15;
        uint32_t d = sdst + (uint32_t)(r * LDA + c * 8) * 2;
        int ok = (r < rows_valid);
        const __half* s = gsrc + (size_t)(ok ? r : 0) * DIM_H + c * 8;
        CP_ASYNC16(d, s, ok ? 16 : 0);
    }
}

__global__ void __launch_bounds__(512, 1)
gemm_tc3(const __half* __restrict__ Ahi,
         const __half* __restrict__ Alo,
         const __half* __restrict__ B,
         const float* __restrict__ bias0,   // 128 cols for ct0 (may be null)
         const float* __restrict__ bias1,   // (n_ct-1)*128 cols (may be null)
         float* __restrict__ C0, int ldc0,
         float* __restrict__ C1, int ldc1,
         int n_rows, int n_ct) {
    extern __shared__ char sm[];
    uint32_t smb = smem_u32(sm);
    const int tid = threadIdx.x;
    const int wid = tid >> 5;
    const int lane = tid & 31;
    const int row0 = blockIdx.x * 128;
    const int rows_valid = n_rows - row0;

    // Prologue: A hi/lo + B tile 0 (group 1); B tile 1 (group 2)
    cp_tile(smb + SM_AHI, Ahi + (size_t)row0 * DIM_H, rows_valid);
    cp_tile(smb + SM_ALO, Alo + (size_t)row0 * DIM_H, rows_valid);
    cp_tile(smb + SM_B, B, 128);
    CP_COMMIT();
    if (n_ct > 1) {
        cp_tile(smb + SM_B + TILE_B, B + 128 * DIM_H, 128);
        CP_COMMIT();
    }
    float* bias_s = reinterpret_cast<float*>(sm + SM_BIAS);
    for (int i = tid; i < n_ct * 128; i += 512) {
        if (i < 128) bias_s[i] = bias0 ? bias0[i] : 0.f;
        else         bias_s[i] = bias1 ? bias1[i - 128] : 0.f;
    }
    if (n_ct > 1) CP_WAIT1(); else CP_WAIT0();
    __syncthreads();

    // 16 warps: wr (0..7) = 16-row group, wc (0..1) = 64-col group
    const int wr = wid & 7;
    const int wc = wid >> 3;

    const int a_m = lane & 15;
    const int a_k = (lane >> 4) * 8;
    const uint32_t offA = (uint32_t)(((wr * 16 + a_m) * LDA + a_k) * 2);

    const int b_n = (lane & 7) + (lane >> 4) * 8;
    const int b_k = ((lane >> 3) & 1) * 8;
    uint32_t offB[4];
#pragma unroll
    for (int p = 0; p < 4; p++)
        offB[p] = (uint32_t)(((wc * 64 + p * 16 + b_n) * LDA + b_k) * 2);

    const int r_in = lane >> 2;
    const int c_in = (lane & 3) * 2;
    const int row_a = row0 + wr * 16 + r_in;
    const int row_b = row_a + 8;

    for (int ct = 0; ct < n_ct; ct++) {
        const uint32_t bbuf = smb + SM_B + (uint32_t)(ct & 1) * TILE_B;

        float acc[8][4];
#pragma unroll
        for (int nt = 0; nt < 8; nt++)
#pragma unroll
            for (int e = 0; e < 4; e++) acc[nt][e] = 0.f;

#pragma unroll
        for (int ks = 0; ks < 8; ks++) {
            const uint32_t kb = ks * 32;
            uint32_t ah0, ah1, ah2, ah3, al0, al1, al2, al3;
            ldsm_x4(ah0, ah1, ah2, ah3, smb + SM_AHI + offA + kb);
            ldsm_x4(al0, al1, al2, al3, smb + SM_ALO + offA + kb);
#pragma unroll
            for (int p = 0; p < 4; p++) {
                uint32_t b0, b1, b2, b3;
                ldsm_x4(b0, b1, b2, b3, bbuf + offB[p] + kb);
                mma_f16(acc[2 * p],     ah0, ah1, ah2, ah3, b0, b1);
                mma_f16(acc[2 * p],     al0, al1, al2, al3, b0, b1);
                mma_f16(acc[2 * p + 1], ah0, ah1, ah2, ah3, b2, b3);
                mma_f16(acc[2 * p + 1], al0, al1, al2, al3, b2, b3);
            }
        }

        // Epilogue for this col tile
        float* Cp = (ct == 0) ? C0 : C1;
        const int ldc = (ct == 0) ? ldc0 : ldc1;
        const int cb_out = (ct == 0) ? wc * 64 : (ct - 1) * 128 + wc * 64;
        const int cb_bias = ct * 128 + wc * 64;
#pragma unroll
        for (int nt = 0; nt < 8; nt++) {
            int cl = nt * 8 + c_in;
            float bx = bias_s[cb_bias + cl], by = bias_s[cb_bias + cl + 1];
            if (row_a < n_rows)
                *reinterpret_cast<float2*>(Cp + (size_t)row_a * ldc + cb_out + cl) =
                    make_float2(acc[nt][0] + bx, acc[nt][1] + by);
            if (row_b < n_rows)
                *reinterpret_cast<float2*>(Cp + (size_t)row_b * ldc + cb_out + cl) =
                    make_float2(acc[nt][2] + bx, acc[nt][3] + by);
        }

        // Prefetch B tile ct+2 into the buffer just freed
        if (ct + 1 < n_ct) {
            __syncthreads();
            if (ct + 2 < n_ct) {
                uint32_t dst = smb + SM_B + (uint32_t)(ct & 1) * TILE_B;
                cp_tile(dst, B + (size_t)(ct + 2) * 128 * DIM_H, 128);
                CP_COMMIT();
                CP_WAIT1();
            } else {
                CP_WAIT0();
            }
            __syncthreads();
        }
    }
}

// ---------------------------------------------------------------------------
// Edge scatter: one warp per edge. messages[dst] += T[src] + b_msg
// ---------------------------------------------------------------------------
__global__ void scatter_kernel(const int* __restrict__ esrc,
                               const int* __restrict__ edst,
                               const float* __restrict__ b_msg, int n_edges) {
    int gwarp = (blockIdx.x * blockDim.x + threadIdx.x) >> 5;
    int lane  = threadIdx.x & 31;
    if (gwarp >= n_edges) return;
    int s = esrc[gwarp];
    int d = edst[gwarp];
    float4 v = reinterpret_cast<const float4*>(g_T + (size_t)s * DIM_H)[lane];
    float4 b = reinterpret_cast<const float4*>(b_msg)[lane];
    v.x += b.x; v.y += b.y; v.z += b.z; v.w += b.w;
    float* p = g_msg + (size_t)d * DIM_H + lane * 4;
    asm volatile("red.global.add.v4.f32 [%0], {%1, %2, %3, %4};"
                 :: "l"(p), "f"(v.x), "f"(v.y), "f"(v.z), "f"(v.w) : "memory");
}

// ---------------------------------------------------------------------------
// Fused GRU gates + LayerNorm + message residual. One warp per node.
// ---------------------------------------------------------------------------
__device__ __forceinline__ float sigmoidf_(float x) {
    return 1.0f / (1.0f + expf(-x));
}

__global__ void gru_ln_kernel(const float* __restrict__ nodes,
                              const float* __restrict__ gamma,
                              const float* __restrict__ beta,
                              float* __restrict__ out, int n_nodes) {
    int gwarp = (blockIdx.x * blockDim.x + threadIdx.x) >> 5;
    int lane  = threadIdx.x & 31;
    if (gwarp >= n_nodes) return;

    size_t base = (size_t)gwarp * DIM_H;
    size_t gb   = (size_t)gwarp * DIM_3H;

    float4 h4  = reinterpret_cast<const float4*>(nodes + base)[lane];
    float4 m4  = reinterpret_cast<const float4*>(g_msg + base)[lane];
    float4 ir4 = reinterpret_cast<const float4*>(g_gi + gb)[lane];
    float4 iz4 = reinterpret_cast<const float4*>(g_gi + gb + 128)[lane];
    float4 in4 = reinterpret_cast<const float4*>(g_gi + gb + 256)[lane];
    float4 hr4 = reinterpret_cast<const float4*>(g_gh + gb)[lane];
    float4 hz4 = reinterpret_cast<const float4*>(g_gh + gb + 128)[lane];
    float4 hn4 = reinterpret_cast<const float4*>(g_gh + gb + 256)[lane];

    float hh[4] = {h4.x, h4.y, h4.z, h4.w};
    float ir[4] = {ir4.x, ir4.y, ir4.z, ir4.w};
    float iz[4] = {iz4.x, iz4.y, iz4.z, iz4.w};
    float in_[4]= {in4.x, in4.y, in4.z, in4.w};
    float hr[4] = {hr4.x, hr4.y, hr4.z, hr4.w};
    float hz[4] = {hz4.x, hz4.y, hz4.z, hz4.w};
    float hn[4] = {hn4.x, hn4.y, hn4.z, hn4.w};

    float hx[4];
    float s = 0.f, s2 = 0.f;
#pragma unroll
    for (int c = 0; c < 4; c++) {
        float r = sigmoidf_(ir[c] + hr[c]);
        float z = sigmoidf_(iz[c] + hz[c]);
        float n = tanhf(in_[c] + r * hn[c]);
        hx[c] = (1.0f - z) * n + z * hh[c];
        s  += hx[c];
        s2 += hx[c] * hx[c];
    }
#pragma unroll
    for (int off = 16; off > 0; off >>= 1) {
        s  += __shfl_xor_sync(0xFFFFFFFF, s,  off);
        s2 += __shfl_xor_sync(0xFFFFFFFF, s2, off);
    }
    float mu   = s  * (1.0f / DIM_H);
    float var  = s2 * (1.0f / DIM_H) - mu * mu;
    float rstd = rsqrtf(var + LN_EPS);

    float4 g4 = reinterpret_cast<const float4*>(gamma)[lane];
    float4 b4 = reinterpret_cast<const float4*>(beta)[lane];
    float gg[4] = {g4.x, g4.y, g4.z, g4.w};
    float bb[4] = {b4.x, b4.y, b4.z, b4.w};
    float mm[4] = {m4.x, m4.y, m4.z, m4.w};

    float o[4];
#pragma unroll
    for (int c = 0; c < 4; c++)
        o[c] = gg[c] * (hx[c] - mu) * rstd + bb[c] + mm[c];

    reinterpret_cast<float4*>(out + base)[lane] =
        make_float4(o[0], o[1], o[2], o[3]);
}

// ---------------------------------------------------------------------------
// Launch (order chosen so gemm1 is launch #6 => captured by ncu -s 5 -c 1)
// ---------------------------------------------------------------------------
extern "C" void kernel_launch(void* const* d_in, const int* in_sizes, int n_in,
                              void* d_out, int out_size) {
    const float* nodes = (const float*)d_in[0];
    const float* W_msg = (const float*)d_in[1];
    const float* b_msg = (const float*)d_in[2];
    const float* w_ih  = (const float*)d_in[3];
    const float* w_hh  = (const float*)d_in[4];
    const float* b_ih  = (const float*)d_in[5];
    const float* b_hh  = (const float*)d_in[6];
    const float* gamma = (const float*)d_in[7];
    const float* beta  = (const float*)d_in[8];
    const int*   esrc  = (const int*)d_in[9];
    const int*   edst  = (const int*)d_in[10];
    float* out = (float*)d_out;

    int n_nodes = in_sizes[0] / DIM_H;
    int n_edges = in_sizes[9];

    float *pT, *pGh, *pMsg, *pGi, *pBias2;
    __half *pNH, *pNL, *pMH, *pML, *pWc, *pWi;
    cudaGetSymbolAddress((void**)&pT,     g_T);
    cudaGetSymbolAddress((void**)&pGh,    g_gh);
    cudaGetSymbolAddress((void**)&pMsg,   g_msg);
    cudaGetSymbolAddress((void**)&pGi,    g_gi);
    cudaGetSymbolAddress((void**)&pBias2, g_bias2);
    cudaGetSymbolAddress((void**)&pNH, g_nhi);
    cudaGetSymbolAddress((void**)&pNL, g_nlo);
    cudaGetSymbolAddress((void**)&pMH, g_mhi);
    cudaGetSymbolAddress((void**)&pML, g_mlo);
    cudaGetSymbolAddress((void**)&pWc, g_Wcat);
    cudaGetSymbolAddress((void**)&pWi, g_Wih);

    cudaFuncSetAttribute(gemm_tc3,
                         cudaFuncAttributeMaxDynamicSharedMemorySize, SM_TOTAL);

    int rt = (n_nodes + 127) / 128;
    int n8 = n_nodes * DIM_H / 8;

    // 1: zero accumulators
    zero_kernel<<<(n_nodes * 32 + 255) / 256, 256>>>(n_nodes);
    // 2-4: weight converts (fp32 -> fp16)
    convW_kernel<<<(DIM_H * DIM_H / 8 + 255) / 256, 256>>>(W_msg, pWc,
                                                           DIM_H * DIM_H / 8);
    convW_kernel<<<(DIM_3H * DIM_H / 8 + 255) / 256, 256>>>(
        w_hh, pWc + 128 * DIM_H, DIM_3H * DIM_H / 8);
    convW_kernel<<<(DIM_3H * DIM_H / 8 + 255) / 256, 256>>>(w_ih, pWi,
                                                            DIM_3H * DIM_H / 8);
    // 5: nodes split + fused column sums
    convertA_kernel<<<(n8 + 255) / 256, 256>>>(nodes, pNH, pNL, n8, 1);
    // 6: [T | gh] = nodes @ [W_msg; w_hh]^T + [0; b_hh]   (profiled launch)
    gemm_tc3<<<rt, 512, SM_TOTAL>>>(pNH, pNL, pWc, nullptr, b_hh,
                                    pT, DIM_H, pGh, DIM_3H, n_nodes, 4);
    // 7: messages[dst] += T[src] + b_msg
    scatter_kernel<<<(n_edges + 7) / 8, 256>>>(esrc, edst, b_msg, n_edges);
    // 8: bias2 = b_ih + w_ih @ mean(nodes)
    bias2_kernel<<<1, DIM_3H>>>(w_ih, b_ih, n_nodes);
    // 9: msg split
    convertA_kernel<<<(n8 + 255) / 256, 256>>>(pMsg, pMH, pML, n8, 0);
    // 10: gi = msg @ w_ih^T + bias2
    gemm_tc3<<<rt, 512, SM_TOTAL>>>(pMH, pML, pWi, pBias2, pBias2 + 128,
                                    pGi, DIM_3H, pGi + 128, DIM_3H, n_nodes, 3);
    // 11: GRU gates + LayerNorm + message residual
    gru_ln_kernel<<<(n_nodes + 7) / 8, 256>>>(nodes, gamma, beta, out, n_nodes);
}

// round 6
// speedup vs baseline: 2.4545x; 1.1031x over previous
#include <cuda_runtime.h>
#include <cuda_fp16.h>
#include <math.h>
#include <stdint.h>

#define DIM_H  128
#define DIM_3H 384
#define MAX_N  50000
#define MAX_E  600000
#define LN_EPS 1e-5f

// ---------------------------------------------------------------------------
// Scratch (device globals: allocation-free per harness rules)
// ---------------------------------------------------------------------------
__device__ float  g_msg[MAX_N * DIM_H];      // segment-summed messages (fp32)
__device__ float  g_colsum[DIM_H];
__device__ float  g_bias2[DIM_3H];           // b_ih + w_ih @ mean(nodes)

__device__ __half g_Th[MAX_N * DIM_H];       // T = nodes @ W_msg^T   (fp16)
__device__ __half g_ghh[MAX_N * DIM_3H];     // gh (fp16)
__device__ __half g_gih[MAX_N * DIM_3H];     // gi (fp16)

__device__ __half g_nhi[MAX_N * DIM_H];      // nodes hi
__device__ __half g_nlo[MAX_N * DIM_H];      // nodes lo
__device__ __half g_mhi[MAX_N * DIM_H];      // msg hi
__device__ __half g_mlo[MAX_N * DIM_H];      // msg lo
__device__ __half g_Wcat[512 * DIM_H];       // [W_msg; w_hh] fp16
__device__ __half g_Wih[DIM_3H * DIM_H];     // w_ih fp16

// ---------------------------------------------------------------------------
// PTX helpers (arch-neutral sm_80+: ldmatrix / mma.sync / cp.async)
// ---------------------------------------------------------------------------
__device__ __forceinline__ uint32_t smem_u32(const void* p) {
    uint32_t a;
    asm("{ .reg .u64 t; cvta.to.shared.u64 t, %1; cvt.u32.u64 %0, t; }"
        : "=r"(a) : "l"(p));
    return a;
}

__device__ __forceinline__ void ldsm_x4(uint32_t& r0, uint32_t& r1,
                                        uint32_t& r2, uint32_t& r3,
                                        uint32_t addr) {
    asm volatile("ldmatrix.sync.aligned.m8n8.x4.shared.b16 {%0,%1,%2,%3}, [%4];"
                 : "=r"(r0), "=r"(r1), "=r"(r2), "=r"(r3) : "r"(addr));
}

__device__ __forceinline__ void mma_f16(float* d, uint32_t a0, uint32_t a1,
                                        uint32_t a2, uint32_t a3,
                                        uint32_t b0, uint32_t b1) {
    asm volatile(
        "mma.sync.aligned.m16n8k16.row.col.f32.f16.f16.f32 "
        "{%0,%1,%2,%3}, {%4,%5,%6,%7}, {%8,%9}, {%0,%1,%2,%3};"
        : "+f"(d[0]), "+f"(d[1]), "+f"(d[2]), "+f"(d[3])
        : "r"(a0), "r"(a1), "r"(a2), "r"(a3), "r"(b0), "r"(b1));
}

#define CP_ASYNC16(dst, src, sz)                                               \
    asm volatile("cp.async.cg.shared.global [%0], [%1], 16, %2;"               \
                 :: "r"(dst), "l"(src), "r"(sz) : "memory")
#define CP_COMMIT() asm volatile("cp.async.commit_group;" ::: "memory")
#define CP_WAIT0()  asm volatile("cp.async.wait_group 0;" ::: "memory")
#define CP_WAIT1()  asm volatile("cp.async.wait_group 1;" ::: "memory")

// 4 halfs -> 4 floats
__device__ __forceinline__ void ld4h(const __half* p, float* o) {
    uint2 u = *reinterpret_cast<const uint2*>(p);
    __half2 a = *reinterpret_cast<__half2*>(&u.x);
    __half2 b = *reinterpret_cast<__half2*>(&u.y);
    float2 fa = __half22float2(a), fb = __half22float2(b);
    o[0] = fa.x; o[1] = fa.y; o[2] = fb.x; o[3] = fb.y;
}

// ---------------------------------------------------------------------------
// Small kernels
// ---------------------------------------------------------------------------
__global__ void zero_kernel(int n_nodes) {
    int i = blockIdx.x * blockDim.x + threadIdx.x;
    float4 z = make_float4(0.f, 0.f, 0.f, 0.f);
    int total = n_nodes * (DIM_H / 4);
    if (i < total) reinterpret_cast<float4*>(g_msg)[i] = z;
    if (i < DIM_H / 4) reinterpret_cast<float4*>(g_colsum)[i] = z;
}

// Convert all three weight matrices fp32 -> fp16 in one kernel.
// Segments (in 8-elem units): W_msg 2048 -> Wcat[0:], w_hh 6144 -> Wcat[16384:],
// w_ih 6144 -> Wih[0:].
__global__ void convW_all(const float* __restrict__ W_msg,
                          const float* __restrict__ w_hh,
                          const float* __restrict__ w_ih) {
    int i = blockIdx.x * blockDim.x + threadIdx.x;
    const float* src;
    __half* dst;
    int j;
    if (i < 2048)       { src = W_msg; dst = g_Wcat;          j = i; }
    else if (i < 8192)  { src = w_hh;  dst = g_Wcat + 16384;  j = i - 2048; }
    else if (i < 14336) { src = w_ih;  dst = g_Wih;           j = i - 8192; }
    else return;
    float4 v0 = reinterpret_cast<const float4*>(src)[j * 2];
    float4 v1 = reinterpret_cast<const float4*>(src)[j * 2 + 1];
    float xs[8] = {v0.x, v0.y, v0.z, v0.w, v1.x, v1.y, v1.z, v1.w};
    uint32_t hb[8];
#pragma unroll
    for (int t = 0; t < 8; t++)
        hb[t] = (uint32_t)__half_as_ushort(__float2half_rn(xs[t]));
    reinterpret_cast<uint4*>(dst)[j] =
        make_uint4(hb[0] | (hb[1] << 16), hb[2] | (hb[3] << 16),
                   hb[4] | (hb[5] << 16), hb[6] | (hb[7] << 16));
}

// fp32 -> fp16 hi/lo split; optional per-column sums (128-col row-major src)
__global__ void convertA_kernel(const float* __restrict__ src,
                                __half* __restrict__ hi,
                                __half* __restrict__ lo,
                                int n8, int do_colsum) {
    __shared__ float cs[DIM_H];
    int tid = threadIdx.x;
    if (do_colsum) {
        if (tid < DIM_H) cs[tid] = 0.f;
        __syncthreads();
    }
    int i = blockIdx.x * blockDim.x + tid;
    if (i < n8) {
        float4 v0 = reinterpret_cast<const float4*>(src)[i * 2];
        float4 v1 = reinterpret_cast<const float4*>(src)[i * 2 + 1];
        float xs[8] = {v0.x, v0.y, v0.z, v0.w, v1.x, v1.y, v1.z, v1.w};
        uint32_t hb[8], lb[8];
#pragma unroll
        for (int t = 0; t < 8; t++) {
            __half h = __float2half_rn(xs[t]);
            __half l = __float2half_rn(xs[t] - __half2float(h));
            hb[t] = (uint32_t)__half_as_ushort(h);
            lb[t] = (uint32_t)__half_as_ushort(l);
        }
        reinterpret_cast<uint4*>(hi)[i] =
            make_uint4(hb[0] | (hb[1] << 16), hb[2] | (hb[3] << 16),
                       hb[4] | (hb[5] << 16), hb[6] | (hb[7] << 16));
        reinterpret_cast<uint4*>(lo)[i] =
            make_uint4(lb[0] | (lb[1] << 16), lb[2] | (lb[3] << 16),
                       lb[4] | (lb[5] << 16), lb[6] | (lb[7] << 16));
        if (do_colsum) {
            int c0 = (i & 15) * 8;
#pragma unroll
            for (int t = 0; t < 8; t++) atomicAdd(&cs[c0 + t], xs[t]);
        }
    }
    if (do_colsum) {
        __syncthreads();
        if (tid < DIM_H) atomicAdd(&g_colsum[tid], cs[tid]);
    }
}

__global__ void bias2_kernel(const float* __restrict__ w_ih,
                             const float* __restrict__ b_ih, int n_nodes) {
    __shared__ float mean_s[DIM_H];
    int tid = threadIdx.x;  // 384 threads
    if (tid < DIM_H) mean_s[tid] = g_colsum[tid] * (1.0f / (float)n_nodes);
    __syncthreads();
    float acc = b_ih[tid];
#pragma unroll 8
    for (int k = 0; k < DIM_H; k++)
        acc = fmaf(w_ih[(size_t)tid * DIM_H + k], mean_s[k], acc);
    g_bias2[tid] = acc;
}

// ---------------------------------------------------------------------------
// Weight-stationary tensor-core GEMM.
// grid = (n_ct, nslices). CTA keeps its B col-tile (128x128 fp16) resident in
// smem and loops over A row-tiles (stride nslices), double-buffering A hi/lo
// via cp.async. D = Ahi@B^T + Alo@B^T + bias, written as fp16.
// ct==0 -> C0 (ldc0, col 0); ct>=1 -> C1 (ldc1, col (ct-1)*128).
// ---------------------------------------------------------------------------
#define LDA 136
#define TILE_B (128 * LDA * 2)        // 34816 B per fp16 tile
#define SM_B    0
#define SM_A0H  TILE_B
#define SM_A0L  (2 * TILE_B)
#define SM_A1H  (3 * TILE_B)
#define SM_A1L  (4 * TILE_B)
#define SM_BIAS (5 * TILE_B)
#define SM_TOTAL (SM_BIAS + 512)

__device__ __forceinline__ void cp_tile(uint32_t sdst, const __half* gsrc,
                                        int rows_valid) {
    int tid = threadIdx.x;
#pragma unroll
    for (int i = 0; i < 4; i++) {
        int idx = tid + i * 512;          // 2048 chunks of 16B
        int r = idx >> 4, c = idx & 15;
        uint32_t d = sdst + (uint32_t)(r * LDA + c * 8) * 2;
        int ok = (r < rows_valid);
        const __half* s = gsrc + (size_t)(ok ? r : 0) * DIM_H + c * 8;
        CP_ASYNC16(d, s, ok ? 16 : 0);
    }
}

__global__ void __launch_bounds__(512, 1)
gemm_ws(const __half* __restrict__ Ahi,
        const __half* __restrict__ Alo,
        const __half* __restrict__ B,
        const float* __restrict__ bias0,
        const float* __restrict__ bias1,
        __half* __restrict__ C0, int ldc0,
        __half* __restrict__ C1, int ldc1,
        int n_rows, int nrt, int nslices) {
    extern __shared__ char sm[];
    uint32_t smb = smem_u32(sm);
    const int tid = threadIdx.x;
    const int wid = tid >> 5;
    const int lane = tid & 31;
    const int ct = blockIdx.x;
    const int slice = blockIdx.y;

    const uint32_t bufH[2] = {SM_A0H, SM_A1H};
    const uint32_t bufL[2] = {SM_A0L, SM_A1L};

    // Prologue: resident B tile + first A tile (one cp.async group)
    cp_tile(smb + SM_B, B + (size_t)ct * 128 * DIM_H, 128);
    {
        int rv = n_rows - slice * 128;
        cp_tile(smb + bufH[0], Ahi + (size_t)slice * 128 * DIM_H, rv);
        cp_tile(smb + bufL[0], Alo + (size_t)slice * 128 * DIM_H, rv);
    }
    CP_COMMIT();

    float* bias_s = reinterpret_cast<float*>(sm + SM_BIAS);
    if (tid < 128)
        bias_s[tid] = (ct == 0) ? (bias0 ? bias0[tid] : 0.f)
                                : (bias1 ? bias1[(ct - 1) * 128 + tid] : 0.f);

    // Warp tiling: 16 warps; wr (0..7) = 16-row group, wc (0..1) = 64-col group
    const int wr = wid & 7;
    const int wc = wid >> 3;

    const int a_m = lane & 15;
    const int a_k = (lane >> 4) * 8;
    const uint32_t offA = (uint32_t)(((wr * 16 + a_m) * LDA + a_k) * 2);

    const int b_n = (lane & 7) + (lane >> 4) * 8;
    const int b_k = ((lane >> 3) & 1) * 8;
    uint32_t offB[4];
#pragma unroll
    for (int p = 0; p < 4; p++)
        offB[p] = (uint32_t)(((wc * 64 + p * 16 + b_n) * LDA + b_k) * 2);

    const int r_in = lane >> 2;
    const int c_in = (lane & 3) * 2;

    __half* Cp;
    int ldc, colbase;
    if (ct == 0) { Cp = C0; ldc = ldc0; colbase = 0; }
    else         { Cp = C1; ldc = ldc1; colbase = (ct - 1) * 128; }

    int nbuf = 0;
    for (int it = slice; it < nrt; it += nslices) {
        int next = it + nslices;
        __syncthreads();  // all warps done reading buffer nbuf^1 (2 iters ago)
        if (next < nrt) {
            int rv = n_rows - next * 128;
            cp_tile(smb + bufH[nbuf ^ 1], Ahi + (size_t)next * 128 * DIM_H, rv);
            cp_tile(smb + bufL[nbuf ^ 1], Alo + (size_t)next * 128 * DIM_H, rv);
            CP_COMMIT();
            CP_WAIT1();   // current tile's group complete
        } else {
            CP_WAIT0();
        }
        __syncthreads();

        const uint32_t ah_b = smb + bufH[nbuf];
        const uint32_t al_b = smb + bufL[nbuf];

        float acc[8][4];
#pragma unroll
        for (int nt = 0; nt < 8; nt++)
#pragma unroll
            for (int e = 0; e < 4; e++) acc[nt][e] = 0.f;

#pragma unroll
        for (int ks = 0; ks < 8; ks++) {
            const uint32_t kb = ks * 32;
            uint32_t ah0, ah1, ah2, ah3, al0, al1, al2, al3;
            ldsm_x4(ah0, ah1, ah2, ah3, ah_b + offA + kb);
            ldsm_x4(al0, al1, al2, al3, al_b + offA + kb);
#pragma unroll
            for (int p = 0; p < 4; p++) {
                uint32_t b0, b1, b2, b3;
                ldsm_x4(b0, b1, b2, b3, smb + SM_B + offB[p] + kb);
                mma_f16(acc[2 * p],     ah0, ah1, ah2, ah3, b0, b1);
                mma_f16(acc[2 * p],     al0, al1, al2, al3, b0, b1);
                mma_f16(acc[2 * p + 1], ah0, ah1, ah2, ah3, b2, b3);
                mma_f16(acc[2 * p + 1], al0, al1, al2, al3, b2, b3);
            }
        }

        // Epilogue: fp16 output, half2 stores
        const int row_a = it * 128 + wr * 16 + r_in;
        const int row_b = row_a + 8;
#pragma unroll
        for (int nt = 0; nt < 8; nt++) {
            int cl = colbase + wc * 64 + nt * 8 + c_in;
            float bx = bias_s[wc * 64 + nt * 8 + c_in];
            float by = bias_s[wc * 64 + nt * 8 + c_in + 1];
            if (row_a < n_rows)
                *reinterpret_cast<__half2*>(Cp + (size_t)row_a * ldc + cl) =
                    __floats2half2_rn(acc[nt][0] + bx, acc[nt][1] + by);
            if (row_b < n_rows)
                *reinterpret_cast<__half2*>(Cp + (size_t)row_b * ldc + cl) =
                    __floats2half2_rn(acc[nt][2] + bx, acc[nt][3] + by);
        }
        nbuf ^= 1;
    }
}

// ---------------------------------------------------------------------------
// Edge scatter: one warp per edge. messages[dst] += T[src] + b_msg
// T is fp16 (256B/row gather); msg accumulates fp32 via red.global.v4.
// ---------------------------------------------------------------------------
__global__ void scatter_kernel(const int* __restrict__ esrc,
                               const int* __restrict__ edst,
                               const float* __restrict__ b_msg, int n_edges) {
    int gwarp = (blockIdx.x * blockDim.x + threadIdx.x) >> 5;
    int lane  = threadIdx.x & 31;
    if (gwarp >= n_edges) return;
    int s = esrc[gwarp];
    int d = edst[gwarp];
    float tv[4];
    ld4h(g_Th + (size_t)s * DIM_H + lane * 4, tv);
    float4 b = reinterpret_cast<const float4*>(b_msg)[lane];
    float* p = g_msg + (size_t)d * DIM_H + lane * 4;
    asm volatile("red.global.add.v4.f32 [%0], {%1, %2, %3, %4};"
                 :: "l"(p), "f"(tv[0] + b.x), "f"(tv[1] + b.y),
                    "f"(tv[2] + b.z), "f"(tv[3] + b.w) : "memory");
}

// ---------------------------------------------------------------------------
// Fused GRU gates + LayerNorm + message residual. One warp per node.
// gi/gh read as fp16.
// ---------------------------------------------------------------------------
__device__ __forceinline__ float sigmoidf_(float x) {
    return 1.0f / (1.0f + expf(-x));
}

__global__ void gru_ln_kernel(const float* __restrict__ nodes,
                              const float* __restrict__ gamma,
                              const float* __restrict__ beta,
                              float* __restrict__ out, int n_nodes) {
    int gwarp = (blockIdx.x * blockDim.x + threadIdx.x) >> 5;
    int lane  = threadIdx.x & 31;
    if (gwarp >= n_nodes) return;

    size_t base = (size_t)gwarp * DIM_H;
    size_t gb   = (size_t)gwarp * DIM_3H;
    int le = lane * 4;

    float4 h4 = reinterpret_cast<const float4*>(nodes + base)[lane];
    float4 m4 = reinterpret_cast<const float4*>(g_msg + base)[lane];

    float ir[4], iz[4], in_[4], hr[4], hz[4], hn[4];
    ld4h(g_gih + gb + le, ir);
    ld4h(g_gih + gb + 128 + le, iz);
    ld4h(g_gih + gb + 256 + le, in_);
    ld4h(g_ghh + gb + le, hr);
    ld4h(g_ghh + gb + 128 + le, hz);
    ld4h(g_ghh + gb + 256 + le, hn);

    float hh[4] = {h4.x, h4.y, h4.z, h4.w};

    float hx[4];
    float s = 0.f, s2 = 0.f;
#pragma unroll
    for (int c = 0; c < 4; c++) {
        float r = sigmoidf_(ir[c] + hr[c]);
        float z = sigmoidf_(iz[c] + hz[c]);
        float n = tanhf(in_[c] + r * hn[c]);
        hx[c] = (1.0f - z) * n + z * hh[c];
        s  += hx[c];
        s2 += hx[c] * hx[c];
    }
#pragma unroll
    for (int off = 16; off > 0; off >>= 1) {
        s  += __shfl_xor_sync(0xFFFFFFFF, s,  off);
        s2 += __shfl_xor_sync(0xFFFFFFFF, s2, off);
    }
    float mu   = s  * (1.0f / DIM_H);
    float var  = s2 * (1.0f / DIM_H) - mu * mu;
    float rstd = rsqrtf(var + LN_EPS);

    float4 g4 = reinterpret_cast<const float4*>(gamma)[lane];
    float4 b4 = reinterpret_cast<const float4*>(beta)[lane];
    float gg[4] = {g4.x, g4.y, g4.z, g4.w};
    float bb[4] = {b4.x, b4.y, b4.z, b4.w};
    float mm[4] = {m4.x, m4.y, m4.z, m4.w};

    float o[4];
#pragma unroll
    for (int c = 0; c < 4; c++)
        o[c] = gg[c] * (hx[c] - mu) * rstd + bb[c] + mm[c];

    reinterpret_cast<float4*>(out + base)[lane] =
        make_float4(o[0], o[1], o[2], o[3]);
}

// ---------------------------------------------------------------------------
// Launch
// ---------------------------------------------------------------------------
extern "C" void kernel_launch(void* const* d_in, const int* in_sizes, int n_in,
                              void* d_out, int out_size) {
    const float* nodes = (const float*)d_in[0];
    const float* W_msg = (const float*)d_in[1];
    const float* b_msg = (const float*)d_in[2];
    const float* w_ih  = (const float*)d_in[3];
    const float* w_hh  = (const float*)d_in[4];
    const float* b_ih  = (const float*)d_in[5];
    const float* b_hh  = (const float*)d_in[6];
    const float* gamma = (const float*)d_in[7];
    const float* beta  = (const float*)d_in[8];
    const int*   esrc  = (const int*)d_in[9];
    const int*   edst  = (const int*)d_in[10];
    float* out = (float*)d_out;

    int n_nodes = in_sizes[0] / DIM_H;
    int n_edges = in_sizes[9];

    float *pMsg, *pBias2;
    __half *pTh, *pGhh, *pGih, *pNH, *pNL, *pMH, *pML, *pWc, *pWi;
    cudaGetSymbolAddress((void**)&pMsg,   g_msg);
    cudaGetSymbolAddress((void**)&pBias2, g_bias2);
    cudaGetSymbolAddress((void**)&pTh,  g_Th);
    cudaGetSymbolAddress((void**)&pGhh, g_ghh);
    cudaGetSymbolAddress((void**)&pGih, g_gih);
    cudaGetSymbolAddress((void**)&pNH,  g_nhi);
    cudaGetSymbolAddress((void**)&pNL,  g_nlo);
    cudaGetSymbolAddress((void**)&pMH,  g_mhi);
    cudaGetSymbolAddress((void**)&pML,  g_mlo);
    cudaGetSymbolAddress((void**)&pWc,  g_Wcat);
    cudaGetSymbolAddress((void**)&pWi,  g_Wih);

    cudaFuncSetAttribute(gemm_ws,
                         cudaFuncAttributeMaxDynamicSharedMemorySize, SM_TOTAL);

    int nrt = (n_nodes + 127) / 128;
    int n8 = n_nodes * DIM_H / 8;

    // 1: zero msg + colsum
    zero_kernel<<<(n_nodes * 32 + 255) / 256, 256>>>(n_nodes);
    // 2: all weight converts
    convW_all<<<(14336 + 255) / 256, 256>>>(W_msg, w_hh, w_ih);
    // 3: nodes split + fused column sums
    convertA_kernel<<<(n8 + 255) / 256, 256>>>(nodes, pNH, pNL, n8, 1);
    // 4: [T | gh] = nodes @ [W_msg; w_hh]^T + [0 | b_hh]  (weight-stationary)
    gemm_ws<<<dim3(4, 37), 512, SM_TOTAL>>>(pNH, pNL, pWc, nullptr, b_hh,
                                            pTh, DIM_H, pGhh, DIM_3H,
                                            n_nodes, nrt, 37);
    // 5: messages[dst] += T[src] + b_msg
    scatter_kernel<<<(n_edges + 7) / 8, 256>>>(esrc, edst, b_msg, n_edges);
    // 6: bias2 = b_ih + w_ih @ mean(nodes)
    bias2_kernel<<<1, DIM_3H>>>(w_ih, b_ih, n_nodes);
    // 7: msg split
    convertA_kernel<<<(n8 + 255) / 256, 256>>>(pMsg, pMH, pML, n8, 0);
    // 8: gi = msg @ w_ih^T + bias2
    gemm_ws<<<dim3(3, 49), 512, SM_TOTAL>>>(pMH, pML, pWi, pBias2, pBias2 + 128,
                                            pGih, DIM_3H, pGih + 128, DIM_3H,
                                            n_nodes, nrt, 49);
    // 9: GRU gates + LayerNorm + message residual
    gru_ln_kernel<<<(n_nodes + 7) / 8, 256>>>(nodes, gamma, beta, out, n_nodes);
}

// round 7
// speedup vs baseline: 3.1278x; 1.2743x over previous
#include <cuda_runtime.h>
#include <cuda_fp16.h>
#include <math.h>
#include <stdint.h>

#define DIM_H  128
#define DIM_3H 384
#define MAX_N  50000
#define MAX_E  600000
#define LN_EPS 1e-5f

// ---------------------------------------------------------------------------
// Scratch (device globals: allocation-free per harness rules)
// ---------------------------------------------------------------------------
__device__ __half g_msg[MAX_N * DIM_H];      // segment-summed messages (fp16!)
__device__ float  g_colsum[DIM_H];
__device__ float  g_bias2[DIM_3H];           // b_ih + w_ih @ mean(nodes)

__device__ __half g_Th[MAX_N * DIM_H];       // T = nodes @ W_msg^T   (fp16)
__device__ __half g_ghh[MAX_N * DIM_3H];     // gh (fp16)
__device__ __half g_gih[MAX_N * DIM_3H];     // gi (fp16)

__device__ __half g_nh[MAX_N * DIM_H];       // nodes fp16
__device__ __half g_Wcat[512 * DIM_H];       // [W_msg; w_hh] fp16
__device__ __half g_Wih[DIM_3H * DIM_H];     // w_ih fp16

// ---------------------------------------------------------------------------
// PTX helpers (arch-neutral sm_80+/sm_90: ldmatrix / mma.sync / cp.async / red)
// ---------------------------------------------------------------------------
__device__ __forceinline__ uint32_t smem_u32(const void* p) {
    uint32_t a;
    asm("{ .reg .u64 t; cvta.to.shared.u64 t, %1; cvt.u32.u64 %0, t; }"
        : "=r"(a) : "l"(p));
    return a;
}

__device__ __forceinline__ void ldsm_x4(uint32_t& r0, uint32_t& r1,
                                        uint32_t& r2, uint32_t& r3,
                                        uint32_t addr) {
    asm volatile("ldmatrix.sync.aligned.m8n8.x4.shared.b16 {%0,%1,%2,%3}, [%4];"
                 : "=r"(r0), "=r"(r1), "=r"(r2), "=r"(r3) : "r"(addr));
}

__device__ __forceinline__ void mma_f16(float* d, uint32_t a0, uint32_t a1,
                                        uint32_t a2, uint32_t a3,
                                        uint32_t b0, uint32_t b1) {
    asm volatile(
        "mma.sync.aligned.m16n8k16.row.col.f32.f16.f16.f32 "
        "{%0,%1,%2,%3}, {%4,%5,%6,%7}, {%8,%9}, {%0,%1,%2,%3};"
        : "+f"(d[0]), "+f"(d[1]), "+f"(d[2]), "+f"(d[3])
        : "r"(a0), "r"(a1), "r"(a2), "r"(a3), "r"(b0), "r"(b1));
}

#define CP_ASYNC16(dst, src, sz)                                               \
    asm volatile("cp.async.cg.shared.global [%0], [%1], 16, %2;"               \
                 :: "r"(dst), "l"(src), "r"(sz) : "memory")
#define CP_COMMIT() asm volatile("cp.async.commit_group;" ::: "memory")
#define CP_WAIT0()  asm volatile("cp.async.wait_group 0;" ::: "memory")
#define CP_WAIT1()  asm volatile("cp.async.wait_group 1;" ::: "memory")

// 4 halfs -> 4 floats
__device__ __forceinline__ void ld4h(const __half* p, float* o) {
    uint2 u = *reinterpret_cast<const uint2*>(p);
    __half2 a = *reinterpret_cast<__half2*>(&u.x);
    __half2 b = *reinterpret_cast<__half2*>(&u.y);
    float2 fa = __half22float2(a), fb = __half22float2(b);
    o[0] = fa.x; o[1] = fa.y; o[2] = fb.x; o[3] = fb.y;
}

// ---------------------------------------------------------------------------
// Small kernels
// ---------------------------------------------------------------------------
__global__ void zero_kernel(int n_nodes) {
    int i = blockIdx.x * blockDim.x + threadIdx.x;
    int total = n_nodes * 16;  // 16 x uint4 (8 halfs) per 128-half row
    if (i < total)
        reinterpret_cast<uint4*>(g_msg)[i] = make_uint4(0, 0, 0, 0);
    if (i < DIM_H / 4)
        reinterpret_cast<float4*>(g_colsum)[i] = make_float4(0.f, 0.f, 0.f, 0.f);
}

// Convert all three weight matrices fp32 -> fp16 in one kernel.
__global__ void convW_all(const float* __restrict__ W_msg,
                          const float* __restrict__ w_hh,
                          const float* __restrict__ w_ih) {
    int i = blockIdx.x * blockDim.x + threadIdx.x;
    const float* src;
    __half* dst;
    int j;
    if (i < 2048)       { src = W_msg; dst = g_Wcat;          j = i; }
    else if (i < 8192)  { src = w_hh;  dst = g_Wcat + 16384;  j = i - 2048; }
    else if (i < 14336) { src = w_ih;  dst = g_Wih;           j = i - 8192; }
    else return;
    float4 v0 = reinterpret_cast<const float4*>(src)[j * 2];
    float4 v1 = reinterpret_cast<const float4*>(src)[j * 2 + 1];
    float xs[8] = {v0.x, v0.y, v0.z, v0.w, v1.x, v1.y, v1.z, v1.w};
    uint32_t hb[8];
#pragma unroll
    for (int t = 0; t < 8; t++)
        hb[t] = (uint32_t)__half_as_ushort(__float2half_rn(xs[t]));
    reinterpret_cast<uint4*>(dst)[j] =
        make_uint4(hb[0] | (hb[1] << 16), hb[2] | (hb[3] << 16),
                   hb[4] | (hb[5] << 16), hb[6] | (hb[7] << 16));
}

// nodes fp32 -> fp16 + fused per-column sums (128-col row-major)
__global__ void convertN_kernel(const float* __restrict__ src, int n8) {
    __shared__ float cs[DIM_H];
    int tid = threadIdx.x;
    if (tid < DIM_H) cs[tid] = 0.f;
    __syncthreads();
    int i = blockIdx.x * blockDim.x + tid;
    if (i < n8) {
        float4 v0 = reinterpret_cast<const float4*>(src)[i * 2];
        float4 v1 = reinterpret_cast<const float4*>(src)[i * 2 + 1];
        float xs[8] = {v0.x, v0.y, v0.z, v0.w, v1.x, v1.y, v1.z, v1.w};
        uint32_t hb[8];
#pragma unroll
        for (int t = 0; t < 8; t++)
            hb[t] = (uint32_t)__half_as_ushort(__float2half_rn(xs[t]));
        reinterpret_cast<uint4*>(g_nh)[i] =
            make_uint4(hb[0] | (hb[1] << 16), hb[2] | (hb[3] << 16),
                       hb[4] | (hb[5] << 16), hb[6] | (hb[7] << 16));
        int c0 = (i & 15) * 8;
#pragma unroll
        for (int t = 0; t < 8; t++) atomicAdd(&cs[c0 + t], xs[t]);
    }
    __syncthreads();
    if (tid < DIM_H) atomicAdd(&g_colsum[tid], cs[tid]);
}

__global__ void bias2_kernel(const float* __restrict__ w_ih,
                             const float* __restrict__ b_ih, int n_nodes) {
    __shared__ float mean_s[DIM_H];
    int tid = threadIdx.x;  // 384 threads
    if (tid < DIM_H) mean_s[tid] = g_colsum[tid] * (1.0f / (float)n_nodes);
    __syncthreads();
    float acc = b_ih[tid];
#pragma unroll 8
    for (int k = 0; k < DIM_H; k++)
        acc = fmaf(w_ih[(size_t)tid * DIM_H + k], mean_s[k], acc);
    g_bias2[tid] = acc;
}

// ---------------------------------------------------------------------------
// Weight-stationary tensor-core GEMM (single fp16 product, fp32 accum).
// grid = (n_ct, nslices). B col-tile resident; A row-tiles double-buffered.
// ct==0 -> C0 (ldc0, col 0); ct>=1 -> C1 (ldc1, col (ct-1)*128). fp16 out.
// ---------------------------------------------------------------------------
#define LDA 136
#define TILE_B (128 * LDA * 2)        // 34816 B per fp16 tile
#define SM_B    0
#define SM_A0   TILE_B
#define SM_A1   (2 * TILE_B)
#define SM_BIAS (3 * TILE_B)
#define SM_TOTAL (SM_BIAS + 512)

__device__ __forceinline__ void cp_tile(uint32_t sdst, const __half* gsrc,
                                        int rows_valid) {
    int tid = threadIdx.x;
#pragma unroll
    for (int i = 0; i < 4; i++) {
        int idx = tid + i * 512;          // 2048 chunks of 16B
        int r = idx >> 4, c = idx & 15;
        uint32_t d = sdst + (uint32_t)(r * LDA + c * 8) * 2;
        int ok = (r < rows_valid);
        const __half* s = gsrc + (size_t)(ok ? r : 0) * DIM_H + c * 8;
        CP_ASYNC16(d, s, ok ? 16 : 0);
    }
}

__global__ void __launch_bounds__(512, 1)
gemm_ws(const __half* __restrict__ A,
        const __half* __restrict__ B,
        const float* __restrict__ bias0,
        const float* __restrict__ bias1,
        __half* __restrict__ C0, int ldc0,
        __half* __restrict__ C1, int ldc1,
        int n_rows, int nrt, int nslices) {
    extern __shared__ char sm[];
    uint32_t smb = smem_u32(sm);
    const int tid = threadIdx.x;
    const int wid = tid >> 5;
    const int lane = tid & 31;
    const int ct = blockIdx.x;
    const int slice = blockIdx.y;

    const uint32_t bufA[2] = {SM_A0, SM_A1};

    // Prologue: resident B tile + first A tile
    cp_tile(smb + SM_B, B + (size_t)ct * 128 * DIM_H, 128);
    cp_tile(smb + bufA[0], A + (size_t)slice * 128 * DIM_H,
            n_rows - slice * 128);
    CP_COMMIT();

    float* bias_s = reinterpret_cast<float*>(sm + SM_BIAS);
    if (tid < 128)
        bias_s[tid] = (ct == 0) ? (bias0 ? bias0[tid] : 0.f)
                                : (bias1 ? bias1[(ct - 1) * 128 + tid] : 0.f);

    // 16 warps: wr (0..7) = 16-row group, wc (0..1) = 64-col group
    const int wr = wid & 7;
    const int wc = wid >> 3;

    const int a_m = lane & 15;
    const int a_k = (lane >> 4) * 8;
    const uint32_t offA = (uint32_t)(((wr * 16 + a_m) * LDA + a_k) * 2);

    const int b_n = (lane & 7) + (lane >> 4) * 8;
    const int b_k = ((lane >> 3) & 1) * 8;
    uint32_t offB[4];
#pragma unroll
    for (int p = 0; p < 4; p++)
        offB[p] = (uint32_t)(((wc * 64 + p * 16 + b_n) * LDA + b_k) * 2);

    const int r_in = lane >> 2;
    const int c_in = (lane & 3) * 2;

    __half* Cp;
    int ldc, colbase;
    if (ct == 0) { Cp = C0; ldc = ldc0; colbase = 0; }
    else         { Cp = C1; ldc = ldc1; colbase = (ct - 1) * 128; }

    int nbuf = 0;
    for (int it = slice; it < nrt; it += nslices) {
        int next = it + nslices;
        __syncthreads();
        if (next < nrt) {
            cp_tile(smb + bufA[nbuf ^ 1], A + (size_t)next * 128 * DIM_H,
                    n_rows - next * 128);
            CP_COMMIT();
            CP_WAIT1();
        } else {
            CP_WAIT0();
        }
        __syncthreads();

        const uint32_t a_b = smb + bufA[nbuf];

        float acc[8][4];
#pragma unroll
        for (int nt = 0; nt < 8; nt++)
#pragma unroll
            for (int e = 0; e < 4; e++) acc[nt][e] = 0.f;

#pragma unroll
        for (int ks = 0; ks < 8; ks++) {
            const uint32_t kb = ks * 32;
            uint32_t a0, a1, a2, a3;
            ldsm_x4(a0, a1, a2, a3, a_b + offA + kb);
#pragma unroll
            for (int p = 0; p < 4; p++) {
                uint32_t b0, b1, b2, b3;
                ldsm_x4(b0, b1, b2, b3, smb + SM_B + offB[p] + kb);
                mma_f16(acc[2 * p],     a0, a1, a2, a3, b0, b1);
                mma_f16(acc[2 * p + 1], a0, a1, a2, a3, b2, b3);
            }
        }

        // Epilogue: fp16 output, half2 stores
        const int row_a = it * 128 + wr * 16 + r_in;
        const int row_b = row_a + 8;
#pragma unroll
        for (int nt = 0; nt < 8; nt++) {
            int cb = wc * 64 + nt * 8 + c_in;
            int cl = colbase + cb;
            float bx = bias_s[cb], by = bias_s[cb + 1];
            if (row_a < n_rows)
                *reinterpret_cast<__half2*>(Cp + (size_t)row_a * ldc + cl) =
                    __floats2half2_rn(acc[nt][0] + bx, acc[nt][1] + by);
            if (row_b < n_rows)
                *reinterpret_cast<__half2*>(Cp + (size_t)row_b * ldc + cl) =
                    __floats2half2_rn(acc[nt][2] + bx, acc[nt][3] + by);
        }
        nbuf ^= 1;
    }
}

// ---------------------------------------------------------------------------
// Edge scatter: TWO edges per warp (16 lanes each).
// messages[dst] += fp16(T[src] + b_msg) via red.global.add.noftz.v4.f16x2
// (16B = 8 halfs per lane -> 1 REDG per lane, 16 lanes per edge).
// ---------------------------------------------------------------------------
__global__ void scatter_kernel(const int* __restrict__ esrc,
                               const int* __restrict__ edst,
                               const float* __restrict__ b_msg, int n_edges) {
    int gwarp = (blockIdx.x * blockDim.x + threadIdx.x) >> 5;
    int lane  = threadIdx.x & 31;
    int e = gwarp * 2 + (lane >> 4);
    int hl = lane & 15;
    if (e >= n_edges) return;
    int s = esrc[e];
    int d = edst[e];
    uint4 tv = *reinterpret_cast<const uint4*>(g_Th + (size_t)s * DIM_H + hl * 8);
    float4 b0 = *reinterpret_cast<const float4*>(b_msg + hl * 8);
    float4 b1 = *reinterpret_cast<const float4*>(b_msg + hl * 8 + 4);
    float bb[8] = {b0.x, b0.y, b0.z, b0.w, b1.x, b1.y, b1.z, b1.w};
    uint32_t tw[4] = {tv.x, tv.y, tv.z, tv.w};
    uint32_t r[4];
#pragma unroll
    for (int j = 0; j < 4; j++) {
        __half2 h = *reinterpret_cast<__half2*>(&tw[j]);
        float2 f = __half22float2(h);
        __half2 o = __floats2half2_rn(f.x + bb[2 * j], f.y + bb[2 * j + 1]);
        r[j] = *reinterpret_cast<uint32_t*>(&o);
    }
    __half* p = g_msg + (size_t)d * DIM_H + hl * 8;
    asm volatile("red.global.add.noftz.v4.f16x2 [%0], {%1, %2, %3, %4};"
                 :: "l"(p), "r"(r[0]), "r"(r[1]), "r"(r[2]), "r"(r[3])
                 : "memory");
}

// ---------------------------------------------------------------------------
// Fused GRU gates + LayerNorm + message residual. One warp per node.
// gi/gh/msg read as fp16.
// ---------------------------------------------------------------------------
__device__ __forceinline__ float sigmoidf_(float x) {
    return 1.0f / (1.0f + expf(-x));
}

__global__ void gru_ln_kernel(const float* __restrict__ nodes,
                              const float* __restrict__ gamma,
                              const float* __restrict__ beta,
                              float* __restrict__ out, int n_nodes) {
    int gwarp = (blockIdx.x * blockDim.x + threadIdx.x) >> 5;
    int lane  = threadIdx.x & 31;
    if (gwarp >= n_nodes) return;

    size_t base = (size_t)gwarp * DIM_H;
    size_t gb   = (size_t)gwarp * DIM_3H;
    int le = lane * 4;

    float4 h4 = reinterpret_cast<const float4*>(nodes + base)[lane];

    float mm[4], ir[4], iz[4], in_[4], hr[4], hz[4], hn[4];
    ld4h(g_msg + base + le, mm);
    ld4h(g_gih + gb + le, ir);
    ld4h(g_gih + gb + 128 + le, iz);
    ld4h(g_gih + gb + 256 + le, in_);
    ld4h(g_ghh + gb + le, hr);
    ld4h(g_ghh + gb + 128 + le, hz);
    ld4h(g_ghh + gb + 256 + le, hn);

    float hh[4] = {h4.x, h4.y, h4.z, h4.w};

    float hx[4];
    float s = 0.f, s2 = 0.f;
#pragma unroll
    for (int c = 0; c < 4; c++) {
        float r = sigmoidf_(ir[c] + hr[c]);
        float z = sigmoidf_(iz[c] + hz[c]);
        float n = tanhf(in_[c] + r * hn[c]);
        hx[c] = (1.0f - z) * n + z * hh[c];
        s  += hx[c];
        s2 += hx[c] * hx[c];
    }
#pragma unroll
    for (int off = 16; off > 0; off >>= 1) {
        s  += __shfl_xor_sync(0xFFFFFFFF, s,  off);
        s2 += __shfl_xor_sync(0xFFFFFFFF, s2, off);
    }
    float mu   = s  * (1.0f / DIM_H);
    float var  = s2 * (1.0f / DIM_H) - mu * mu;
    float rstd = rsqrtf(var + LN_EPS);

    float4 g4 = reinterpret_cast<const float4*>(gamma)[lane];
    float4 b4 = reinterpret_cast<const float4*>(beta)[lane];
    float gg[4] = {g4.x, g4.y, g4.z, g4.w};
    float bb[4] = {b4.x, b4.y, b4.z, b4.w};

    float o[4];
#pragma unroll
    for (int c = 0; c < 4; c++)
        o[c] = gg[c] * (hx[c] - mu) * rstd + bb[c] + mm[c];

    reinterpret_cast<float4*>(out + base)[lane] =
        make_float4(o[0], o[1], o[2], o[3]);
}

// ---------------------------------------------------------------------------
// Launch (order: scatter is launch #6 => captured by ncu -s 5 -c 1)
// ---------------------------------------------------------------------------
extern "C" void kernel_launch(void* const* d_in, const int* in_sizes, int n_in,
                              void* d_out, int out_size) {
    const float* nodes = (const float*)d_in[0];
    const float* W_msg = (const float*)d_in[1];
    const float* b_msg = (const float*)d_in[2];
    const float* w_ih  = (const float*)d_in[3];
    const float* w_hh  = (const float*)d_in[4];
    const float* b_ih  = (const float*)d_in[5];
    const float* b_hh  = (const float*)d_in[6];
    const float* gamma = (const float*)d_in[7];
    const float* beta  = (const float*)d_in[8];
    const int*   esrc  = (const int*)d_in[9];
    const int*   edst  = (const int*)d_in[10];
    float* out = (float*)d_out;

    int n_nodes = in_sizes[0] / DIM_H;
    int n_edges = in_sizes[9];

    float *pBias2;
    __half *pMsg, *pTh, *pGhh, *pGih, *pNh, *pWc, *pWi;
    cudaGetSymbolAddress((void**)&pBias2, g_bias2);
    cudaGetSymbolAddress((void**)&pMsg, g_msg);
    cudaGetSymbolAddress((void**)&pTh,  g_Th);
    cudaGetSymbolAddress((void**)&pGhh, g_ghh);
    cudaGetSymbolAddress((void**)&pGih, g_gih);
    cudaGetSymbolAddress((void**)&pNh,  g_nh);
    cudaGetSymbolAddress((void**)&pWc,  g_Wcat);
    cudaGetSymbolAddress((void**)&pWi,  g_Wih);

    cudaFuncSetAttribute(gemm_ws,
                         cudaFuncAttributeMaxDynamicSharedMemorySize, SM_TOTAL);

    int nrt = (n_nodes + 127) / 128;
    int n8 = n_nodes * DIM_H / 8;

    // 1: zero msg (fp16) + colsum
    zero_kernel<<<(n_nodes * 16 + 255) / 256, 256>>>(n_nodes);
    // 2: all weight converts
    convW_all<<<(14336 + 255) / 256, 256>>>(W_msg, w_hh, w_ih);
    // 3: nodes -> fp16 + fused column sums
    convertN_kernel<<<(n8 + 255) / 256, 256>>>(nodes, n8);
    // 4: bias2 = b_ih + w_ih @ mean(nodes)
    bias2_kernel<<<1, DIM_3H>>>(w_ih, b_ih, n_nodes);
    // 5: [T | gh] = nodes @ [W_msg; w_hh]^T + [0 | b_hh]
    gemm_ws<<<dim3(4, 37), 512, SM_TOTAL>>>(pNh, pWc, nullptr, b_hh,
                                            pTh, DIM_H, pGhh, DIM_3H,
                                            n_nodes, nrt, 37);
    // 6: messages[dst] += T[src] + b_msg   (fp16x2 vector reductions; profiled)
    scatter_kernel<<<((n_edges + 1) / 2 * 32 + 255) / 256, 256>>>(
        esrc, edst, b_msg, n_edges);
    // 7: gi = msg @ w_ih^T + bias2  (msg fp16 exact -> single product)
    gemm_ws<<<dim3(3, 49), 512, SM_TOTAL>>>(pMsg, pWi, pBias2, pBias2 + 128,
                                            pGih, DIM_3H, pGih + 128, DIM_3H,
                                            n_nodes, nrt, 49);
    // 8: GRU gates + LayerNorm + message residual
    gru_ln_kernel<<<(n_nodes + 7) / 8, 256>>>(nodes, gamma, beta, out, n_nodes);
}

// round 8
// speedup vs baseline: 3.8135x; 1.2192x over previous
#include <cuda_runtime.h>
#include <cuda_fp16.h>
#include <math.h>
#include <stdint.h>

#define DIM_H  128
#define DIM_3H 384
#define MAX_N  50000
#define MAX_E  600000
#define LN_EPS 1e-5f

// ---------------------------------------------------------------------------
// Scratch (device globals: allocation-free per harness rules)
// ---------------------------------------------------------------------------
__device__ __half g_msg[MAX_N * DIM_H];      // segment-summed messages (fp16)
__device__ float  g_colsum[DIM_H];
__device__ float  g_bias2[DIM_3H];           // b_ih + w_ih @ mean(nodes)

__device__ __half g_Th[MAX_N * DIM_H];       // T = nodes @ W_msg^T   (fp16)
__device__ __half g_ghh[MAX_N * DIM_3H];     // gh (fp16)
__device__ __half g_gih[MAX_N * DIM_3H];     // gi (fp16)

__device__ __half g_nh[MAX_N * DIM_H];       // nodes fp16
__device__ __half g_Wcat[512 * DIM_H];       // [W_msg; w_hh] fp16
__device__ __half g_Wih[DIM_3H * DIM_H];     // w_ih fp16

// ---------------------------------------------------------------------------
// PTX helpers (arch-neutral sm_80+/sm_90: ldmatrix / mma.sync / cp.async / red)
// ---------------------------------------------------------------------------
__device__ __forceinline__ uint32_t smem_u32(const void* p) {
    uint32_t a;
    asm("{ .reg .u64 t; cvta.to.shared.u64 t, %1; cvt.u32.u64 %0, t; }"
        : "=r"(a) : "l"(p));
    return a;
}

__device__ __forceinline__ void ldsm_x4(uint32_t& r0, uint32_t& r1,
                                        uint32_t& r2, uint32_t& r3,
                                        uint32_t addr) {
    asm volatile("ldmatrix.sync.aligned.m8n8.x4.shared.b16 {%0,%1,%2,%3}, [%4];"
                 : "=r"(r0), "=r"(r1), "=r"(r2), "=r"(r3) : "r"(addr));
}

__device__ __forceinline__ void mma_f16(float* d, uint32_t a0, uint32_t a1,
                                        uint32_t a2, uint32_t a3,
                                        uint32_t b0, uint32_t b1) {
    asm volatile(
        "mma.sync.aligned.m16n8k16.row.col.f32.f16.f16.f32 "
        "{%0,%1,%2,%3}, {%4,%5,%6,%7}, {%8,%9}, {%0,%1,%2,%3};"
        : "+f"(d[0]), "+f"(d[1]), "+f"(d[2]), "+f"(d[3])
        : "r"(a0), "r"(a1), "r"(a2), "r"(a3), "r"(b0), "r"(b1));
}

#define CP_ASYNC16(dst, src, sz)                                               \
    asm volatile("cp.async.cg.shared.global [%0], [%1], 16, %2;"               \
                 :: "r"(dst), "l"(src), "r"(sz) : "memory")
#define CP_COMMIT() asm volatile("cp.async.commit_group;" ::: "memory")
#define CP_WAIT0()  asm volatile("cp.async.wait_group 0;" ::: "memory")
#define CP_WAIT1()  asm volatile("cp.async.wait_group 1;" ::: "memory")

// 4 halfs -> 4 floats
__device__ __forceinline__ void ld4h(const __half* p, float* o) {
    uint2 u = *reinterpret_cast<const uint2*>(p);
    __half2 a = *reinterpret_cast<__half2*>(&u.x);
    __half2 b = *reinterpret_cast<__half2*>(&u.y);
    float2 fa = __half22float2(a), fb = __half22float2(b);
    o[0] = fa.x; o[1] = fa.y; o[2] = fb.x; o[3] = fb.y;
}

// ---------------------------------------------------------------------------
// Small kernels
// ---------------------------------------------------------------------------
__global__ void zero_kernel(int n_nodes) {
    int i = blockIdx.x * blockDim.x + threadIdx.x;
    int total = n_nodes * 16;  // 16 x uint4 (8 halfs) per 128-half row
    if (i < total)
        reinterpret_cast<uint4*>(g_msg)[i] = make_uint4(0, 0, 0, 0);
    if (i < DIM_H / 4)
        reinterpret_cast<float4*>(g_colsum)[i] = make_float4(0.f, 0.f, 0.f, 0.f);
}

// Convert all three weight matrices fp32 -> fp16 in one kernel.
__global__ void convW_all(const float* __restrict__ W_msg,
                          const float* __restrict__ w_hh,
                          const float* __restrict__ w_ih) {
    int i = blockIdx.x * blockDim.x + threadIdx.x;
    const float* src;
    __half* dst;
    int j;
    if (i < 2048)       { src = W_msg; dst = g_Wcat;          j = i; }
    else if (i < 8192)  { src = w_hh;  dst = g_Wcat + 16384;  j = i - 2048; }
    else if (i < 14336) { src = w_ih;  dst = g_Wih;           j = i - 8192; }
    else return;
    float4 v0 = reinterpret_cast<const float4*>(src)[j * 2];
    float4 v1 = reinterpret_cast<const float4*>(src)[j * 2 + 1];
    float xs[8] = {v0.x, v0.y, v0.z, v0.w, v1.x, v1.y, v1.z, v1.w};
    uint32_t hb[8];
#pragma unroll
    for (int t = 0; t < 8; t++)
        hb[t] = (uint32_t)__half_as_ushort(__float2half_rn(xs[t]));
    reinterpret_cast<uint4*>(dst)[j] =
        make_uint4(hb[0] | (hb[1] << 16), hb[2] | (hb[3] << 16),
                   hb[4] | (hb[5] << 16), hb[6] | (hb[7] << 16));
}

// nodes fp32 -> fp16 + fused per-column sums (128-col row-major).
// Lanes l and l+16 cover the same 8 columns -> combine via shfl before smem.
__global__ void convertN_kernel(const float* __restrict__ src, int n8) {
    __shared__ float cs[DIM_H];
    int tid = threadIdx.x;
    if (tid < DIM_H) cs[tid] = 0.f;
    __syncthreads();
    int i = blockIdx.x * blockDim.x + tid;
    int lane = tid & 31;
    float xs[8] = {0.f, 0.f, 0.f, 0.f, 0.f, 0.f, 0.f, 0.f};
    if (i < n8) {
        float4 v0 = reinterpret_cast<const float4*>(src)[i * 2];
        float4 v1 = reinterpret_cast<const float4*>(src)[i * 2 + 1];
        xs[0] = v0.x; xs[1] = v0.y; xs[2] = v0.z; xs[3] = v0.w;
        xs[4] = v1.x; xs[5] = v1.y; xs[6] = v1.z; xs[7] = v1.w;
        uint32_t hb[8];
#pragma unroll
        for (int t = 0; t < 8; t++)
            hb[t] = (uint32_t)__half_as_ushort(__float2half_rn(xs[t]));
        reinterpret_cast<uint4*>(g_nh)[i] =
            make_uint4(hb[0] | (hb[1] << 16), hb[2] | (hb[3] << 16),
                       hb[4] | (hb[5] << 16), hb[6] | (hb[7] << 16));
    }
    // pairwise combine lanes l and l+16 (same column group)
#pragma unroll
    for (int t = 0; t < 8; t++)
        xs[t] += __shfl_down_sync(0xFFFFFFFF, xs[t], 16);
    if (lane < 16) {
        int c0 = lane * 8;
#pragma unroll
        for (int t = 0; t < 8; t++) atomicAdd(&cs[c0 + t], xs[t]);
    }
    __syncthreads();
    if (tid < DIM_H) atomicAdd(&g_colsum[tid], cs[tid]);
}

// bias2 = b_ih + w_ih @ (colsum / n): warp-per-row, coalesced, shuffle-reduced.
// launch: <<<3, 1024>>> (96 warps, 4 rows each)
__global__ void bias2_fast(const float* __restrict__ w_ih,
                           const float* __restrict__ b_ih, int n_nodes) {
    __shared__ float mean_s[DIM_H];
    int tid = threadIdx.x;
    if (tid < DIM_H) mean_s[tid] = g_colsum[tid] * (1.0f / (float)n_nodes);
    __syncthreads();
    int warp = (blockIdx.x * blockDim.x + tid) >> 5;  // 0..95
    int lane = tid & 31;
    for (int r = warp; r < DIM_3H; r += 96) {
        float acc = 0.f;
#pragma unroll
        for (int j = 0; j < 4; j++) {
            int k = lane + j * 32;
            acc = fmaf(w_ih[(size_t)r * DIM_H + k], mean_s[k], acc);
        }
#pragma unroll
        for (int off = 16; off > 0; off >>= 1)
            acc += __shfl_xor_sync(0xFFFFFFFF, acc, off);
        if (lane == 0) g_bias2[r] = acc + b_ih[r];
    }
}

// ---------------------------------------------------------------------------
// Weight-stationary tensor-core GEMM (single fp16 product, fp32 accum).
// grid = (n_ct, nslices). B col-tile resident; A row-tiles double-buffered.
// ct==0 -> C0 (ldc0, col 0); ct>=1 -> C1 (ldc1, col (ct-1)*128). fp16 out.
// ---------------------------------------------------------------------------
#define LDA 136
#define TILE_B (128 * LDA * 2)        // 34816 B per fp16 tile
#define SM_B    0
#define SM_A0   TILE_B
#define SM_A1   (2 * TILE_B)
#define SM_BIAS (3 * TILE_B)
#define SM_TOTAL (SM_BIAS + 512)

__device__ __forceinline__ void cp_tile(uint32_t sdst, const __half* gsrc,
                                        int rows_valid) {
    int tid = threadIdx.x;
#pragma unroll
    for (int i = 0; i < 4; i++) {
        int idx = tid + i * 512;          // 2048 chunks of 16B
        int r = idx >> 4, c = idx & 15;
        uint32_t d = sdst + (uint32_t)(r * LDA + c * 8) * 2;
        int ok = (r < rows_valid);
        const __half* s = gsrc + (size_t)(ok ? r : 0) * DIM_H + c * 8;
        CP_ASYNC16(d, s, ok ? 16 : 0);
    }
}

__global__ void __launch_bounds__(512, 1)
gemm_ws(const __half* __restrict__ A,
        const __half* __restrict__ B,
        const float* __restrict__ bias0,
        const float* __restrict__ bias1,
        __half* __restrict__ C0, int ldc0,
        __half* __restrict__ C1, int ldc1,
        int n_rows, int nrt, int nslices) {
    extern __shared__ char sm[];
    uint32_t smb = smem_u32(sm);
    const int tid = threadIdx.x;
    const int wid = tid >> 5;
    const int lane = tid & 31;
    const int ct = blockIdx.x;
    const int slice = blockIdx.y;

    const uint32_t bufA[2] = {SM_A0, SM_A1};

    // Prologue: resident B tile + first A tile
    cp_tile(smb + SM_B, B + (size_t)ct * 128 * DIM_H, 128);
    cp_tile(smb + bufA[0], A + (size_t)slice * 128 * DIM_H,
            n_rows - slice * 128);
    CP_COMMIT();

    float* bias_s = reinterpret_cast<float*>(sm + SM_BIAS);
    if (tid < 128)
        bias_s[tid] = (ct == 0) ? (bias0 ? bias0[tid] : 0.f)
                                : (bias1 ? bias1[(ct - 1) * 128 + tid] : 0.f);

    // 16 warps: wr (0..7) = 16-row group, wc (0..1) = 64-col group
    const int wr = wid & 7;
    const int wc = wid >> 3;

    const int a_m = lane & 15;
    const int a_k = (lane >> 4) * 8;
    const uint32_t offA = (uint32_t)(((wr * 16 + a_m) * LDA + a_k) * 2);

    const int b_n = (lane & 7) + (lane >> 4) * 8;
    const int b_k = ((lane >> 3) & 1) * 8;
    uint32_t offB[4];
#pragma unroll
    for (int p = 0; p < 4; p++)
        offB[p] = (uint32_t)(((wc * 64 + p * 16 + b_n) * LDA + b_k) * 2);

    const int r_in = lane >> 2;
    const int c_in = (lane & 3) * 2;

    __half* Cp;
    int ldc, colbase;
    if (ct == 0) { Cp = C0; ldc = ldc0; colbase = 0; }
    else         { Cp = C1; ldc = ldc1; colbase = (ct - 1) * 128; }

    int nbuf = 0;
    for (int it = slice; it < nrt; it += nslices) {
        int next = it + nslices;
        __syncthreads();
        if (next < nrt) {
            cp_tile(smb + bufA[nbuf ^ 1], A + (size_t)next * 128 * DIM_H,
                    n_rows - next * 128);
            CP_COMMIT();
            CP_WAIT1();
        } else {
            CP_WAIT0();
        }
        __syncthreads();

        const uint32_t a_b = smb + bufA[nbuf];

        float acc[8][4];
#pragma unroll
        for (int nt = 0; nt < 8; nt++)
#pragma unroll
            for (int e = 0; e < 4; e++) acc[nt][e] = 0.f;

#pragma unroll
        for (int ks = 0; ks < 8; ks++) {
            const uint32_t kb = ks * 32;
            uint32_t a0, a1, a2, a3;
            ldsm_x4(a0, a1, a2, a3, a_b + offA + kb);
#pragma unroll
            for (int p = 0; p < 4; p++) {
                uint32_t b0, b1, b2, b3;
                ldsm_x4(b0, b1, b2, b3, smb + SM_B + offB[p] + kb);
                mma_f16(acc[2 * p],     a0, a1, a2, a3, b0, b1);
                mma_f16(acc[2 * p + 1], a0, a1, a2, a3, b2, b3);
            }
        }

        // Epilogue: fp16 output, half2 stores
        const int row_a = it * 128 + wr * 16 + r_in;
        const int row_b = row_a + 8;
#pragma unroll
        for (int nt = 0; nt < 8; nt++) {
            int cb = wc * 64 + nt * 8 + c_in;
            int cl = colbase + cb;
            float bx = bias_s[cb], by = bias_s[cb + 1];
            if (row_a < n_rows)
                *reinterpret_cast<__half2*>(Cp + (size_t)row_a * ldc + cl) =
                    __floats2half2_rn(acc[nt][0] + bx, acc[nt][1] + by);
            if (row_b < n_rows)
                *reinterpret_cast<__half2*>(Cp + (size_t)row_b * ldc + cl) =
                    __floats2half2_rn(acc[nt][2] + bx, acc[nt][3] + by);
        }
        nbuf ^= 1;
    }
}

// ---------------------------------------------------------------------------
// Edge scatter: TWO edges per warp (16 lanes each).
// messages[dst] += fp16(T[src] + b_msg) via red.global.add.noftz.v4.f16x2
// ---------------------------------------------------------------------------
__global__ void scatter_kernel(const int* __restrict__ esrc,
                               const int* __restrict__ edst,
                               const float* __restrict__ b_msg, int n_edges) {
    int gwarp = (blockIdx.x * blockDim.x + threadIdx.x) >> 5;
    int lane  = threadIdx.x & 31;
    int e = gwarp * 2 + (lane >> 4);
    int hl = lane & 15;
    if (e >= n_edges) return;
    int s = esrc[e];
    int d = edst[e];
    uint4 tv = *reinterpret_cast<const uint4*>(g_Th + (size_t)s * DIM_H + hl * 8);
    float4 b0 = *reinterpret_cast<const float4*>(b_msg + hl * 8);
    float4 b1 = *reinterpret_cast<const float4*>(b_msg + hl * 8 + 4);
    float bb[8] = {b0.x, b0.y, b0.z, b0.w, b1.x, b1.y, b1.z, b1.w};
    uint32_t tw[4] = {tv.x, tv.y, tv.z, tv.w};
    uint32_t r[4];
#pragma unroll
    for (int j = 0; j < 4; j++) {
        __half2 h = *reinterpret_cast<__half2*>(&tw[j]);
        float2 f = __half22float2(h);
        __half2 o = __floats2half2_rn(f.x + bb[2 * j], f.y + bb[2 * j + 1]);
        r[j] = *reinterpret_cast<uint32_t*>(&o);
    }
    __half* p = g_msg + (size_t)d * DIM_H + hl * 8;
    asm volatile("red.global.add.noftz.v4.f16x2 [%0], {%1, %2, %3, %4};"
                 :: "l"(p), "r"(r[0]), "r"(r[1]), "r"(r[2]), "r"(r[3])
                 : "memory");
}

// ---------------------------------------------------------------------------
// Fused GRU gates + LayerNorm + message residual. One warp per node.
// ---------------------------------------------------------------------------
__device__ __forceinline__ float sigmoidf_(float x) {
    return 1.0f / (1.0f + expf(-x));
}

__global__ void gru_ln_kernel(const float* __restrict__ nodes,
                              const float* __restrict__ gamma,
                              const float* __restrict__ beta,
                              float* __restrict__ out, int n_nodes) {
    int gwarp = (blockIdx.x * blockDim.x + threadIdx.x) >> 5;
    int lane  = threadIdx.x & 31;
    if (gwarp >= n_nodes) return;

    size_t base = (size_t)gwarp * DIM_H;
    size_t gb   = (size_t)gwarp * DIM_3H;
    int le = lane * 4;

    float4 h4 = reinterpret_cast<const float4*>(nodes + base)[lane];

    float mm[4], ir[4], iz[4], in_[4], hr[4], hz[4], hn[4];
    ld4h(g_msg + base + le, mm);
    ld4h(g_gih + gb + le, ir);
    ld4h(g_gih + gb + 128 + le, iz);
    ld4h(g_gih + gb + 256 + le, in_);
    ld4h(g_ghh + gb + le, hr);
    ld4h(g_ghh + gb + 128 + le, hz);
    ld4h(g_ghh + gb + 256 + le, hn);

    float hh[4] = {h4.x, h4.y, h4.z, h4.w};

    float hx[4];
    float s = 0.f, s2 = 0.f;
#pragma unroll
    for (int c = 0; c < 4; c++) {
        float r = sigmoidf_(ir[c] + hr[c]);
        float z = sigmoidf_(iz[c] + hz[c]);
        float n = tanhf(in_[c] + r * hn[c]);
        hx[c] = (1.0f - z) * n + z * hh[c];
        s  += hx[c];
        s2 += hx[c] * hx[c];
    }
#pragma unroll
    for (int off = 16; off > 0; off >>= 1) {
        s  += __shfl_xor_sync(0xFFFFFFFF, s,  off);
        s2 += __shfl_xor_sync(0xFFFFFFFF, s2, off);
    }
    float mu   = s  * (1.0f / DIM_H);
    float var  = s2 * (1.0f / DIM_H) - mu * mu;
    float rstd = rsqrtf(var + LN_EPS);

    float4 g4 = reinterpret_cast<const float4*>(gamma)[lane];
    float4 b4 = reinterpret_cast<const float4*>(beta)[lane];
    float gg[4] = {g4.x, g4.y, g4.z, g4.w};
    float bb[4] = {b4.x, b4.y, b4.z, b4.w};

    float o[4];
#pragma unroll
    for (int c = 0; c < 4; c++)
        o[c] = gg[c] * (hx[c] - mu) * rstd + bb[c] + mm[c];

    reinterpret_cast<float4*>(out + base)[lane] =
        make_float4(o[0], o[1], o[2], o[3]);
}

// ---------------------------------------------------------------------------
// Launch (order: scatter is launch #6 => captured by ncu -s 5 -c 1)
// ---------------------------------------------------------------------------
extern "C" void kernel_launch(void* const* d_in, const int* in_sizes, int n_in,
                              void* d_out, int out_size) {
    const float* nodes = (const float*)d_in[0];
    const float* W_msg = (const float*)d_in[1];
    const float* b_msg = (const float*)d_in[2];
    const float* w_ih  = (const float*)d_in[3];
    const float* w_hh  = (const float*)d_in[4];
    const float* b_ih  = (const float*)d_in[5];
    const float* b_hh  = (const float*)d_in[6];
    const float* gamma = (const float*)d_in[7];
    const float* beta  = (const float*)d_in[8];
    const int*   esrc  = (const int*)d_in[9];
    const int*   edst  = (const int*)d_in[10];
    float* out = (float*)d_out;

    int n_nodes = in_sizes[0] / DIM_H;
    int n_edges = in_sizes[9];

    float *pBias2;
    __half *pMsg, *pTh, *pGhh, *pGih, *pNh, *pWc, *pWi;
    cudaGetSymbolAddress((void**)&pBias2, g_bias2);
    cudaGetSymbolAddress((void**)&pMsg, g_msg);
    cudaGetSymbolAddress((void**)&pTh,  g_Th);
    cudaGetSymbolAddress((void**)&pGhh, g_ghh);
    cudaGetSymbolAddress((void**)&pGih, g_gih);
    cudaGetSymbolAddress((void**)&pNh,  g_nh);
    cudaGetSymbolAddress((void**)&pWc,  g_Wcat);
    cudaGetSymbolAddress((void**)&pWi,  g_Wih);

    cudaFuncSetAttribute(gemm_ws,
                         cudaFuncAttributeMaxDynamicSharedMemorySize, SM_TOTAL);

    int nrt = (n_nodes + 127) / 128;
    int n8 = n_nodes * DIM_H / 8;

    // 1: zero msg (fp16) + colsum
    zero_kernel<<<(n_nodes * 16 + 255) / 256, 256>>>(n_nodes);
    // 2: all weight converts
    convW_all<<<(14336 + 255) / 256, 256>>>(W_msg, w_hh, w_ih);
    // 3: nodes -> fp16 + fused column sums
    convertN_kernel<<<(n8 + 255) / 256, 256>>>(nodes, n8);
    // 4: bias2 = b_ih + w_ih @ mean(nodes)  (parallel warp-per-row)
    bias2_fast<<<3, 1024>>>(w_ih, b_ih, n_nodes);
    // 5: [T | gh] = nodes @ [W_msg; w_hh]^T + [0 | b_hh]
    gemm_ws<<<dim3(4, 37), 512, SM_TOTAL>>>(pNh, pWc, nullptr, b_hh,
                                            pTh, DIM_H, pGhh, DIM_3H,
                                            n_nodes, nrt, 37);
    // 6: messages[dst] += T[src] + b_msg   (fp16x2 vector reductions; profiled)
    scatter_kernel<<<((n_edges + 1) / 2 * 32 + 255) / 256, 256>>>(
        esrc, edst, b_msg, n_edges);
    // 7: gi = msg @ w_ih^T + bias2  (msg fp16 exact -> single product)
    gemm_ws<<<dim3(3, 49), 512, SM_TOTAL>>>(pMsg, pWi, pBias2, pBias2 + 128,
                                            pGih, DIM_3H, pGih + 128, DIM_3H,
                                            n_nodes, nrt, 49);
    // 8: GRU gates + LayerNorm + message residual
    gru_ln_kernel<<<(n_nodes + 7) / 8, 256>>>(nodes, gamma, beta, out, n_nodes);
}

// round 9
// speedup vs baseline: 3.9581x; 1.0379x over previous
#include <cuda_runtime.h>
#include <cuda_fp16.h>
#include <math.h>
#include <stdint.h>

#define DIM_H  128
#define DIM_3H 384
#define MAX_N  50000
#define MAX_E  600000
#define LN_EPS 1e-5f

// ---------------------------------------------------------------------------
// Scratch (device globals: allocation-free per harness rules)
// ---------------------------------------------------------------------------
__device__ __half g_msg[MAX_N * DIM_H];      // segment-summed messages (fp16)
__device__ float  g_colsum[DIM_H];
__device__ float  g_bias2[DIM_3H];           // b_ih + w_ih @ mean(nodes)

__device__ __half g_Th[MAX_N * DIM_H];       // T = nodes @ W_msg^T   (fp16)
__device__ __half g_ghh[MAX_N * DIM_3H];     // gh (fp16)
__device__ __half g_gih[MAX_N * DIM_3H];     // gi (fp16)

__device__ __half g_nh[MAX_N * DIM_H];       // nodes fp16
__device__ __half g_Wcat[512 * DIM_H];       // [W_msg; w_hh] fp16
__device__ __half g_Wih[DIM_3H * DIM_H];     // w_ih fp16

// ---------------------------------------------------------------------------
// PTX helpers (arch-neutral sm_80+/sm_90: ldmatrix / mma.sync / cp.async / red)
// ---------------------------------------------------------------------------
__device__ __forceinline__ uint32_t smem_u32(const void* p) {
    uint32_t a;
    asm("{ .reg .u64 t; cvta.to.shared.u64 t, %1; cvt.u32.u64 %0, t; }"
        : "=r"(a) : "l"(p));
    return a;
}

__device__ __forceinline__ void ldsm_x4(uint32_t& r0, uint32_t& r1,
                                        uint32_t& r2, uint32_t& r3,
                                        uint32_t addr) {
    asm volatile("ldmatrix.sync.aligned.m8n8.x4.shared.b16 {%0,%1,%2,%3}, [%4];"
                 : "=r"(r0), "=r"(r1), "=r"(r2), "=r"(r3) : "r"(addr));
}

__device__ __forceinline__ void mma_f16(float* d, uint32_t a0, uint32_t a1,
                                        uint32_t a2, uint32_t a3,
                                        uint32_t b0, uint32_t b1) {
    asm volatile(
        "mma.sync.aligned.m16n8k16.row.col.f32.f16.f16.f32 "
        "{%0,%1,%2,%3}, {%4,%5,%6,%7}, {%8,%9}, {%0,%1,%2,%3};"
        : "+f"(d[0]), "+f"(d[1]), "+f"(d[2]), "+f"(d[3])
        : "r"(a0), "r"(a1), "r"(a2), "r"(a3), "r"(b0), "r"(b1));
}

#define CP_ASYNC16(dst, src, sz)                                               \
    asm volatile("cp.async.cg.shared.global [%0], [%1], 16, %2;"               \
                 :: "r"(dst), "l"(src), "r"(sz) : "memory")
#define CP_COMMIT() asm volatile("cp.async.commit_group;" ::: "memory")
#define CP_WAIT0()  asm volatile("cp.async.wait_group 0;" ::: "memory")
#define CP_WAIT1()  asm volatile("cp.async.wait_group 1;" ::: "memory")

// 4 halfs -> 4 floats
__device__ __forceinline__ void ld4h(const __half* p, float* o) {
    uint2 u = *reinterpret_cast<const uint2*>(p);
    __half2 a = *reinterpret_cast<__half2*>(&u.x);
    __half2 b = *reinterpret_cast<__half2*>(&u.y);
    float2 fa = __half22float2(a), fb = __half22float2(b);
    o[0] = fa.x; o[1] = fa.y; o[2] = fb.x; o[3] = fb.y;
}

// ---------------------------------------------------------------------------
// Small kernels
// ---------------------------------------------------------------------------

// Convert all three weight matrices fp32 -> fp16; also zero g_colsum
// (runs before convertNZ which accumulates into it).
__global__ void convW_all(const float* __restrict__ W_msg,
                          const float* __restrict__ w_hh,
                          const float* __restrict__ w_ih) {
    int i = blockIdx.x * blockDim.x + threadIdx.x;
    if (i < DIM_H / 4)
        reinterpret_cast<float4*>(g_colsum)[i] = make_float4(0.f, 0.f, 0.f, 0.f);
    const float* src;
    __half* dst;
    int j;
    if (i < 2048)       { src = W_msg; dst = g_Wcat;          j = i; }
    else if (i < 8192)  { src = w_hh;  dst = g_Wcat + 16384;  j = i - 2048; }
    else if (i < 14336) { src = w_ih;  dst = g_Wih;           j = i - 8192; }
    else return;
    float4 v0 = reinterpret_cast<const float4*>(src)[j * 2];
    float4 v1 = reinterpret_cast<const float4*>(src)[j * 2 + 1];
    float xs[8] = {v0.x, v0.y, v0.z, v0.w, v1.x, v1.y, v1.z, v1.w};
    uint32_t hb[8];
#pragma unroll
    for (int t = 0; t < 8; t++)
        hb[t] = (uint32_t)__half_as_ushort(__float2half_rn(xs[t]));
    reinterpret_cast<uint4*>(dst)[j] =
        make_uint4(hb[0] | (hb[1] << 16), hb[2] | (hb[3] << 16),
                   hb[4] | (hb[5] << 16), hb[6] | (hb[7] << 16));
}

// nodes fp32 -> fp16 + fused column sums + fused zeroing of g_msg.
// n8 = n_nodes*16 threads; thread i also zeroes g_msg uint4 #i.
__global__ void convertNZ_kernel(const float* __restrict__ src, int n8) {
    __shared__ float cs[DIM_H];
    int tid = threadIdx.x;
    if (tid < DIM_H) cs[tid] = 0.f;
    __syncthreads();
    int i = blockIdx.x * blockDim.x + tid;
    int lane = tid & 31;
    float xs[8] = {0.f, 0.f, 0.f, 0.f, 0.f, 0.f, 0.f, 0.f};
    if (i < n8) {
        reinterpret_cast<uint4*>(g_msg)[i] = make_uint4(0, 0, 0, 0);
        float4 v0 = reinterpret_cast<const float4*>(src)[i * 2];
        float4 v1 = reinterpret_cast<const float4*>(src)[i * 2 + 1];
        xs[0] = v0.x; xs[1] = v0.y; xs[2] = v0.z; xs[3] = v0.w;
        xs[4] = v1.x; xs[5] = v1.y; xs[6] = v1.z; xs[7] = v1.w;
        uint32_t hb[8];
#pragma unroll
        for (int t = 0; t < 8; t++)
            hb[t] = (uint32_t)__half_as_ushort(__float2half_rn(xs[t]));
        reinterpret_cast<uint4*>(g_nh)[i] =
            make_uint4(hb[0] | (hb[1] << 16), hb[2] | (hb[3] << 16),
                       hb[4] | (hb[5] << 16), hb[6] | (hb[7] << 16));
    }
    // pairwise combine lanes l and l+16 (same column group)
#pragma unroll
    for (int t = 0; t < 8; t++)
        xs[t] += __shfl_down_sync(0xFFFFFFFF, xs[t], 16);
    if (lane < 16) {
        int c0 = lane * 8;
#pragma unroll
        for (int t = 0; t < 8; t++) atomicAdd(&cs[c0 + t], xs[t]);
    }
    __syncthreads();
    if (tid < DIM_H) atomicAdd(&g_colsum[tid], cs[tid]);
}

// bias2 = b_ih + w_ih @ (colsum / n): one warp per row. launch <<<12, 1024>>>
__global__ void bias2_fast(const float* __restrict__ w_ih,
                           const float* __restrict__ b_ih, int n_nodes) {
    __shared__ float mean_s[DIM_H];
    int tid = threadIdx.x;
    if (tid < DIM_H) mean_s[tid] = g_colsum[tid] * (1.0f / (float)n_nodes);
    __syncthreads();
    int r = (blockIdx.x * blockDim.x + tid) >> 5;  // 0..383
    int lane = tid & 31;
    if (r >= DIM_3H) return;
    float acc = 0.f;
#pragma unroll
    for (int j = 0; j < 4; j++) {
        int k = lane + j * 32;
        acc = fmaf(w_ih[(size_t)r * DIM_H + k], mean_s[k], acc);
    }
#pragma unroll
    for (int off = 16; off > 0; off >>= 1)
        acc += __shfl_xor_sync(0xFFFFFFFF, acc, off);
    if (lane == 0) g_bias2[r] = acc + b_ih[r];
}

// ---------------------------------------------------------------------------
// Weight-stationary tensor-core GEMM (single fp16 product, fp32 accum).
// grid = (n_ct, nslices). B col-tile resident; A row-tiles double-buffered.
// ct==0 -> C0 (ldc0, col 0); ct>=1 -> C1 (ldc1, col (ct-1)*128). fp16 out.
// ---------------------------------------------------------------------------
#define LDA 136
#define TILE_B (128 * LDA * 2)        // 34816 B per fp16 tile
#define SM_B    0
#define SM_A0   TILE_B
#define SM_A1   (2 * TILE_B)
#define SM_BIAS (3 * TILE_B)
#define SM_TOTAL (SM_BIAS + 512)

__device__ __forceinline__ void cp_tile(uint32_t sdst, const __half* gsrc,
                                        int rows_valid) {
    int tid = threadIdx.x;
#pragma unroll
    for (int i = 0; i < 4; i++) {
        int idx = tid + i * 512;          // 2048 chunks of 16B
        int r = idx >> 4, c = idx & 15;
        uint32_t d = sdst + (uint32_t)(r * LDA + c * 8) * 2;
        int ok = (r < rows_valid);
        const __half* s = gsrc + (size_t)(ok ? r : 0) * DIM_H + c * 8;
        CP_ASYNC16(d, s, ok ? 16 : 0);
    }
}

__global__ void __launch_bounds__(512, 1)
gemm_ws(const __half* __restrict__ A,
        const __half* __restrict__ B,
        const float* __restrict__ bias0,
        const float* __restrict__ bias1,
        __half* __restrict__ C0, int ldc0,
        __half* __restrict__ C1, int ldc1,
        int n_rows, int nrt, int nslices) {
    extern __shared__ char sm[];
    uint32_t smb = smem_u32(sm);
    const int tid = threadIdx.x;
    const int wid = tid >> 5;
    const int lane = tid & 31;
    const int ct = blockIdx.x;
    const int slice = blockIdx.y;

    const uint32_t bufA[2] = {SM_A0, SM_A1};

    // Prologue: resident B tile + first A tile
    cp_tile(smb + SM_B, B + (size_t)ct * 128 * DIM_H, 128);
    cp_tile(smb + bufA[0], A + (size_t)slice * 128 * DIM_H,
            n_rows - slice * 128);
    CP_COMMIT();

    float* bias_s = reinterpret_cast<float*>(sm + SM_BIAS);
    if (tid < 128)
        bias_s[tid] = (ct == 0) ? (bias0 ? bias0[tid] : 0.f)
                                : (bias1 ? bias1[(ct - 1) * 128 + tid] : 0.f);

    // 16 warps: wr (0..7) = 16-row group, wc (0..1) = 64-col group
    const int wr = wid & 7;
    const int wc = wid >> 3;

    const int a_m = lane & 15;
    const int a_k = (lane >> 4) * 8;
    const uint32_t offA = (uint32_t)(((wr * 16 + a_m) * LDA + a_k) * 2);

    const int b_n = (lane & 7) + (lane >> 4) * 8;
    const int b_k = ((lane >> 3) & 1) * 8;
    uint32_t offB[4];
#pragma unroll
    for (int p = 0; p < 4; p++)
        offB[p] = (uint32_t)(((wc * 64 + p * 16 + b_n) * LDA + b_k) * 2);

    const int r_in = lane >> 2;
    const int c_in = (lane & 3) * 2;

    __half* Cp;
    int ldc, colbase;
    if (ct == 0) { Cp = C0; ldc = ldc0; colbase = 0; }
    else         { Cp = C1; ldc = ldc1; colbase = (ct - 1) * 128; }

    int nbuf = 0;
    for (int it = slice; it < nrt; it += nslices) {
        int next = it + nslices;
        __syncthreads();
        if (next < nrt) {
            cp_tile(smb + bufA[nbuf ^ 1], A + (size_t)next * 128 * DIM_H,
                    n_rows - next * 128);
            CP_COMMIT();
            CP_WAIT1();
        } else {
            CP_WAIT0();
        }
        __syncthreads();

        const uint32_t a_b = smb + bufA[nbuf];

        float acc[8][4];
#pragma unroll
        for (int nt = 0; nt < 8; nt++)
#pragma unroll
            for (int e = 0; e < 4; e++) acc[nt][e] = 0.f;

#pragma unroll
        for (int ks = 0; ks < 8; ks++) {
            const uint32_t kb = ks * 32;
            uint32_t a0, a1, a2, a3;
            ldsm_x4(a0, a1, a2, a3, a_b + offA + kb);
#pragma unroll
            for (int p = 0; p < 4; p++) {
                uint32_t b0, b1, b2, b3;
                ldsm_x4(b0, b1, b2, b3, smb + SM_B + offB[p] + kb);
                mma_f16(acc[2 * p],     a0, a1, a2, a3, b0, b1);
                mma_f16(acc[2 * p + 1], a0, a1, a2, a3, b2, b3);
            }
        }

        // Epilogue: fp16 output, half2 stores
        const int row_a = it * 128 + wr * 16 + r_in;
        const int row_b = row_a + 8;
#pragma unroll
        for (int nt = 0; nt < 8; nt++) {
            int cb = wc * 64 + nt * 8 + c_in;
            int cl = colbase + cb;
            float bx = bias_s[cb], by = bias_s[cb + 1];
            if (row_a < n_rows)
                *reinterpret_cast<__half2*>(Cp + (size_t)row_a * ldc + cl) =
                    __floats2half2_rn(acc[nt][0] + bx, acc[nt][1] + by);
            if (row_b < n_rows)
                *reinterpret_cast<__half2*>(Cp + (size_t)row_b * ldc + cl) =
                    __floats2half2_rn(acc[nt][2] + bx, acc[nt][3] + by);
        }
        nbuf ^= 1;
    }
}

// ---------------------------------------------------------------------------
// Edge scatter: TWO edges per warp (16 lanes each).
// messages[dst] += fp16(T[src] + b_msg) via red.global.add.noftz.v4.f16x2
// ---------------------------------------------------------------------------
__global__ void scatter_kernel(const int* __restrict__ esrc,
                               const int* __restrict__ edst,
                               const float* __restrict__ b_msg, int n_edges) {
    int gwarp = (blockIdx.x * blockDim.x + threadIdx.x) >> 5;
    int lane  = threadIdx.x & 31;
    int e = gwarp * 2 + (lane >> 4);
    int hl = lane & 15;
    if (e >= n_edges) return;
    int s = esrc[e];
    int d = edst[e];
    uint4 tv = *reinterpret_cast<const uint4*>(g_Th + (size_t)s * DIM_H + hl * 8);
    float4 b0 = *reinterpret_cast<const float4*>(b_msg + hl * 8);
    float4 b1 = *reinterpret_cast<const float4*>(b_msg + hl * 8 + 4);
    float bb[8] = {b0.x, b0.y, b0.z, b0.w, b1.x, b1.y, b1.z, b1.w};
    uint32_t tw[4] = {tv.x, tv.y, tv.z, tv.w};
    uint32_t r[4];
#pragma unroll
    for (int j = 0; j < 4; j++) {
        __half2 h = *reinterpret_cast<__half2*>(&tw[j]);
        float2 f = __half22float2(h);
        __half2 o = __floats2half2_rn(f.x + bb[2 * j], f.y + bb[2 * j + 1]);
        r[j] = *reinterpret_cast<uint32_t*>(&o);
    }
    __half* p = g_msg + (size_t)d * DIM_H + hl * 8;
    asm volatile("red.global.add.noftz.v4.f16x2 [%0], {%1, %2, %3, %4};"
                 :: "l"(p), "r"(r[0]), "r"(r[1]), "r"(r[2]), "r"(r[3])
                 : "memory");
}

// ---------------------------------------------------------------------------
// Fused GRU gates + LayerNorm + message residual. One warp per node.
// ---------------------------------------------------------------------------
__device__ __forceinline__ float sigmoidf_(float x) {
    return 1.0f / (1.0f + expf(-x));
}

__global__ void gru_ln_kernel(const float* __restrict__ nodes,
                              const float* __restrict__ gamma,
                              const float* __restrict__ beta,
                              float* __restrict__ out, int n_nodes) {
    int gwarp = (blockIdx.x * blockDim.x + threadIdx.x) >> 5;
    int lane  = threadIdx.x & 31;
    if (gwarp >= n_nodes) return;

    size_t base = (size_t)gwarp * DIM_H;
    size_t gb   = (size_t)gwarp * DIM_3H;
    int le = lane * 4;

    float4 h4 = reinterpret_cast<const float4*>(nodes + base)[lane];

    float mm[4], ir[4], iz[4], in_[4], hr[4], hz[4], hn[4];
    ld4h(g_msg + base + le, mm);
    ld4h(g_gih + gb + le, ir);
    ld4h(g_gih + gb + 128 + le, iz);
    ld4h(g_gih + gb + 256 + le, in_);
    ld4h(g_ghh + gb + le, hr);
    ld4h(g_ghh + gb + 128 + le, hz);
    ld4h(g_ghh + gb + 256 + le, hn);

    float hh[4] = {h4.x, h4.y, h4.z, h4.w};

    float hx[4];
    float s = 0.f, s2 = 0.f;
#pragma unroll
    for (int c = 0; c < 4; c++) {
        float r = sigmoidf_(ir[c] + hr[c]);
        float z = sigmoidf_(iz[c] + hz[c]);
        float n = tanhf(in_[c] + r * hn[c]);
        hx[c] = (1.0f - z) * n + z * hh[c];
        s  += hx[c];
        s2 += hx[c] * hx[c];
    }
#pragma unroll
    for (int off = 16; off > 0; off >>= 1) {
        s  += __shfl_xor_sync(0xFFFFFFFF, s,  off);
        s2 += __shfl_xor_sync(0xFFFFFFFF, s2, off);
    }
    float mu   = s  * (1.0f / DIM_H);
    float var  = s2 * (1.0f / DIM_H) - mu * mu;
    float rstd = rsqrtf(var + LN_EPS);

    float4 g4 = reinterpret_cast<const float4*>(gamma)[lane];
    float4 b4 = reinterpret_cast<const float4*>(beta)[lane];
    float gg[4] = {g4.x, g4.y, g4.z, g4.w};
    float bb[4] = {b4.x, b4.y, b4.z, b4.w};

    float o[4];
#pragma unroll
    for (int c = 0; c < 4; c++)
        o[c] = gg[c] * (hx[c] - mu) * rstd + bb[c] + mm[c];

    reinterpret_cast<float4*>(out + base)[lane] =
        make_float4(o[0], o[1], o[2], o[3]);
}

// ---------------------------------------------------------------------------
// Launch. Dependency graph:
//   convW ─┬─> gemmT ──> scatter ──> gemm2 ──┐
//   convNZ ┤       └──(fork) gemmGH ─(join)──┴─> gru_ln
//          └─> bias2 ──────────────> gemm2
// gemmGH runs on a forked stream, overlapping scatter+gemm2.
// ---------------------------------------------------------------------------
extern "C" void kernel_launch(void* const* d_in, const int* in_sizes, int n_in,
                              void* d_out, int out_size) {
    const float* nodes = (const float*)d_in[0];
    const float* W_msg = (const float*)d_in[1];
    const float* b_msg = (const float*)d_in[2];
    const float* w_ih  = (const float*)d_in[3];
    const float* w_hh  = (const float*)d_in[4];
    const float* b_ih  = (const float*)d_in[5];
    const float* b_hh  = (const float*)d_in[6];
    const float* gamma = (const float*)d_in[7];
    const float* beta  = (const float*)d_in[8];
    const int*   esrc  = (const int*)d_in[9];
    const int*   edst  = (const int*)d_in[10];
    float* out = (float*)d_out;

    int n_nodes = in_sizes[0] / DIM_H;
    int n_edges = in_sizes[9];

    float *pBias2;
    __half *pMsg, *pTh, *pGhh, *pGih, *pNh, *pWc, *pWi;
    cudaGetSymbolAddress((void**)&pBias2, g_bias2);
    cudaGetSymbolAddress((void**)&pMsg, g_msg);
    cudaGetSymbolAddress((void**)&pTh,  g_Th);
    cudaGetSymbolAddress((void**)&pGhh, g_ghh);
    cudaGetSymbolAddress((void**)&pGih, g_gih);
    cudaGetSymbolAddress((void**)&pNh,  g_nh);
    cudaGetSymbolAddress((void**)&pWc,  g_Wcat);
    cudaGetSymbolAddress((void**)&pWi,  g_Wih);

    cudaFuncSetAttribute(gemm_ws,
                         cudaFuncAttributeMaxDynamicSharedMemorySize, SM_TOTAL);

    // One-time host-side resources for the capture fork (host alloc only;
    // same launch sequence every call -> deterministic graph).
    static cudaStream_t s2 = nullptr;
    static cudaEvent_t evFork = nullptr, evJoin = nullptr;
    if (s2 == nullptr) {
        cudaStreamCreateWithFlags(&s2, cudaStreamNonBlocking);
        cudaEventCreateWithFlags(&evFork, cudaEventDisableTiming);
        cudaEventCreateWithFlags(&evJoin, cudaEventDisableTiming);
    }

    int nrt = (n_nodes + 127) / 128;
    int n8 = n_nodes * DIM_H / 8;

    // 1: weight converts + colsum zero
    convW_all<<<(14336 + 255) / 256, 256>>>(W_msg, w_hh, w_ih);
    // 2: nodes -> fp16 + column sums + zero g_msg
    convertNZ_kernel<<<(n8 + 255) / 256, 256>>>(nodes, n8);
    // 3: bias2 = b_ih + w_ih @ mean(nodes)  (one warp per row)
    bias2_fast<<<12, 1024>>>(w_ih, b_ih, n_nodes);
    // 4: T = nodes @ W_msg^T  (1 col tile, one wave)
    gemm_ws<<<dim3(1, 148), 512, SM_TOTAL>>>(pNh, pWc, nullptr, nullptr,
                                             pTh, DIM_H, pTh, DIM_H,
                                             n_nodes, nrt, 148);

    // Fork: gh = nodes @ w_hh^T + b_hh on s2, overlapping scatter + gemm2
    cudaEventRecord(evFork, 0);
    cudaStreamWaitEvent(s2, evFork, 0);
    gemm_ws<<<dim3(3, 49), 512, SM_TOTAL, s2>>>(
        pNh, pWc + 128 * DIM_H, b_hh, b_hh + 128,
        pGhh, DIM_3H, pGhh + 128, DIM_3H, n_nodes, nrt, 49);
    cudaEventRecord(evJoin, s2);

    // 5: messages[dst] += T[src] + b_msg  (fp16x2 vector reductions)
    scatter_kernel<<<((n_edges + 1) / 2 * 32 + 255) / 256, 256>>>(
        esrc, edst, b_msg, n_edges);
    // 6: gi = msg @ w_ih^T + bias2
    gemm_ws<<<dim3(3, 49), 512, SM_TOTAL>>>(pMsg, pWi, pBias2, pBias2 + 128,
                                            pGih, DIM_3H, pGih + 128, DIM_3H,
                                            n_nodes, nrt, 49);

    // Join: gru_ln needs gh from s2
    cudaStreamWaitEvent(0, evJoin, 0);
    // 7: GRU gates + LayerNorm + message residual
    gru_ln_kernel<<<(n_nodes + 7) / 8, 256>>>(nodes, gamma, beta, out, n_nodes);
}

// round 11
// speedup vs baseline: 4.1184x; 1.0405x over previous
#include <cuda_runtime.h>
#include <cuda_fp16.h>
#include <math.h>
#include <stdint.h>

#define DIM_H  128
#define DIM_3H 384
#define MAX_N  50000
#define MAX_E  600000
#define LN_EPS 1e-5f

// ---------------------------------------------------------------------------
// Scratch (device globals: allocation-free per harness rules)
// g_colsum contract: zero at kernel_launch entry (zero-init on load; re-zeroed
// by gru_ln at the end of every run) -> prep kernel may accumulate directly.
// ---------------------------------------------------------------------------
__device__ __align__(256) __half g_msg[MAX_N * DIM_H];   // messages (fp16)
__device__ float  g_colsum[DIM_H];
__device__ float  g_bias2[DIM_3H];            // b_ih + w_ih @ mean(nodes)

__device__ __align__(256) __half g_Th[MAX_N * DIM_H];    // T (fp16)
__device__ __align__(256) __half g_ghh[MAX_N * DIM_3H];  // gh (fp16)
__device__ __align__(256) __half g_gih[MAX_N * DIM_3H];  // gi (fp16)

__device__ __align__(256) __half g_nh[MAX_N * DIM_H];    // nodes fp16
__device__ __align__(256) __half g_Wcat[512 * DIM_H];    // [W_msg; w_hh] fp16
__device__ __align__(256) __half g_Wih[DIM_3H * DIM_H];  // w_ih fp16

// ---------------------------------------------------------------------------
// PTX helpers (arch-neutral sm_80+/sm_90: ldmatrix / mma.sync / cp.async / red)
// ---------------------------------------------------------------------------
__device__ __forceinline__ uint32_t smem_u32(const void* p) {
    uint32_t a;
    asm("{ .reg .u64 t; cvta.to.shared.u64 t, %1; cvt.u32.u64 %0, t; }"
        : "=r"(a) : "l"(p));
    return a;
}

__device__ __forceinline__ void ldsm_x4(uint32_t& r0, uint32_t& r1,
                                        uint32_t& r2, uint32_t& r3,
                                        uint32_t addr) {
    asm volatile("ldmatrix.sync.aligned.m8n8.x4.shared.b16 {%0,%1,%2,%3}, [%4];"
                 : "=r"(r0), "=r"(r1), "=r"(r2), "=r"(r3) : "r"(addr));
}

__device__ __forceinline__ void mma_f16(float* d, uint32_t a0, uint32_t a1,
                                        uint32_t a2, uint32_t a3,
                                        uint32_t b0, uint32_t b1) {
    asm volatile(
        "mma.sync.aligned.m16n8k16.row.col.f32.f16.f16.f32 "
        "{%0,%1,%2,%3}, {%4,%5,%6,%7}, {%8,%9}, {%0,%1,%2,%3};"
        : "+f"(d[0]), "+f"(d[1]), "+f"(d[2]), "+f"(d[3])
        : "r"(a0), "r"(a1), "r"(a2), "r"(a3), "r"(b0), "r"(b1));
}

#define CP_ASYNC16(dst, src, sz)                                               \
    asm volatile("cp.async.cg.shared.global [%0], [%1], 16, %2;"               \
                 :: "r"(dst), "l"(src), "r"(sz) : "memory")
#define CP_COMMIT() asm volatile("cp.async.commit_group;" ::: "memory")
#define CP_WAIT0()  asm volatile("cp.async.wait_group 0;" ::: "memory")
#define CP_WAIT1()  asm volatile("cp.async.wait_group 1;" ::: "memory")

// 4 halfs -> 4 floats
__device__ __forceinline__ void ld4h(const __half* p, float* o) {
    uint2 u = *reinterpret_cast<const uint2*>(p);
    __half2 a = *reinterpret_cast<__half2*>(&u.x);
    __half2 b = *reinterpret_cast<__half2*>(&u.y);
    float2 fa = __half22float2(a), fb = __half22float2(b);
    o[0] = fa.x; o[1] = fa.y; o[2] = fb.x; o[3] = fb.y;
}

// ---------------------------------------------------------------------------
// Fused prep kernel. Blocks [0, nbN): nodes fp32->fp16 + column-sum atomics
// + zero g_msg. Blocks [nbN, nbN+56): all weight matrices fp32->fp16.
// ---------------------------------------------------------------------------
__global__ void prep_kernel(const float* __restrict__ nodes,
                            const float* __restrict__ W_msg,
                            const float* __restrict__ w_hh,
                            const float* __restrict__ w_ih,
                            int n8, int nbN) {
    int tid = threadIdx.x;
    if ((int)blockIdx.x >= nbN) {
        int i = (blockIdx.x - nbN) * 256 + tid;
        const float* src;
        __half* dst;
        int j;
        if (i < 2048)       { src = W_msg; dst = g_Wcat;          j = i; }
        else if (i < 8192)  { src = w_hh;  dst = g_Wcat + 16384;  j = i - 2048; }
        else if (i < 14336) { src = w_ih;  dst = g_Wih;           j = i - 8192; }
        else return;
        float4 v0 = reinterpret_cast<const float4*>(src)[j * 2];
        float4 v1 = reinterpret_cast<const float4*>(src)[j * 2 + 1];
        float xs[8] = {v0.x, v0.y, v0.z, v0.w, v1.x, v1.y, v1.z, v1.w};
        uint32_t hb[8];
#pragma unroll
        for (int t = 0; t < 8; t++)
            hb[t] = (uint32_t)__half_as_ushort(__float2half_rn(xs[t]));
        reinterpret_cast<uint4*>(dst)[j] =
            make_uint4(hb[0] | (hb[1] << 16), hb[2] | (hb[3] << 16),
                       hb[4] | (hb[5] << 16), hb[6] | (hb[7] << 16));
        return;
    }
    // nodes part
    __shared__ float cs[DIM_H];
    if (tid < DIM_H) cs[tid] = 0.f;
    __syncthreads();
    int i = blockIdx.x * 256 + tid;
    int lane = tid & 31;
    float xs[8] = {0.f, 0.f, 0.f, 0.f, 0.f, 0.f, 0.f, 0.f};
    if (i < n8) {
        reinterpret_cast<uint4*>(g_msg)[i] = make_uint4(0, 0, 0, 0);
        float4 v0 = reinterpret_cast<const float4*>(nodes)[i * 2];
        float4 v1 = reinterpret_cast<const float4*>(nodes)[i * 2 + 1];
        xs[0] = v0.x; xs[1] = v0.y; xs[2] = v0.z; xs[3] = v0.w;
        xs[4] = v1.x; xs[5] = v1.y; xs[6] = v1.z; xs[7] = v1.w;
        uint32_t hb[8];
#pragma unroll
        for (int t = 0; t < 8; t++)
            hb[t] = (uint32_t)__half_as_ushort(__float2half_rn(xs[t]));
        reinterpret_cast<uint4*>(g_nh)[i] =
            make_uint4(hb[0] | (hb[1] << 16), hb[2] | (hb[3] << 16),
                       hb[4] | (hb[5] << 16), hb[6] | (hb[7] << 16));
    }
#pragma unroll
    for (int t = 0; t < 8; t++)
        xs[t] += __shfl_down_sync(0xFFFFFFFF, xs[t], 16);
    if (lane < 16) {
        int c0 = lane * 8;
#pragma unroll
        for (int t = 0; t < 8; t++) atomicAdd(&cs[c0 + t], xs[t]);
    }
    __syncthreads();
    if (tid < DIM_H) atomicAdd(&g_colsum[tid], cs[tid]);
}

// bias2 = b_ih + w_ih @ (colsum / n): one warp per row. launch <<<12, 1024>>>
__global__ void bias2_fast(const float* __restrict__ w_ih,
                           const float* __restrict__ b_ih, int n_nodes) {
    __shared__ float mean_s[DIM_H];
    int tid = threadIdx.x;
    if (tid < DIM_H) mean_s[tid] = g_colsum[tid] * (1.0f / (float)n_nodes);
    __syncthreads();
    int r = (blockIdx.x * blockDim.x + tid) >> 5;  // 0..383
    int lane = tid & 31;
    if (r >= DIM_3H) return;
    float acc = 0.f;
#pragma unroll
    for (int j = 0; j < 4; j++) {
        int k = lane + j * 32;
        acc = fmaf(w_ih[(size_t)r * DIM_H + k], mean_s[k], acc);
    }
#pragma unroll
    for (int off = 16; off > 0; off >>= 1)
        acc += __shfl_xor_sync(0xFFFFFFFF, acc, off);
    if (lane == 0) g_bias2[r] = acc + b_ih[r];
}

// ---------------------------------------------------------------------------
// Weight-stationary tensor-core GEMM (single fp16 product, fp32 accum).
// ---------------------------------------------------------------------------
#define LDA 136
#define TILE_B (128 * LDA * 2)        // 34816 B per fp16 tile
#define SM_B    0
#define SM_A0   TILE_B
#define SM_A1   (2 * TILE_B)
#define SM_BIAS (3 * TILE_B)
#define SM_TOTAL (SM_BIAS + 512)

__device__ __forceinline__ void cp_tile(uint32_t sdst, const __half* gsrc,
                                        int rows_valid) {
    int tid = threadIdx.x;
#pragma unroll
    for (int i = 0; i < 4; i++) {
        int idx = tid + i * 512;          // 2048 chunks of 16B
        int r = idx >> 4, c = idx & 15;
        uint32_t d = sdst + (uint32_t)(r * LDA + c * 8) * 2;
        int ok = (r < rows_valid);
        const __half* s = gsrc + (size_t)(ok ? r : 0) * DIM_H + c * 8;
        CP_ASYNC16(d, s, ok ? 16 : 0);
    }
}

__global__ void __launch_bounds__(512, 1)
gemm_ws(const __half* __restrict__ A,
        const __half* __restrict__ B,
        const float* __restrict__ bias0,
        const float* __restrict__ bias1,
        __half* __restrict__ C0, int ldc0,
        __half* __restrict__ C1, int ldc1,
        int n_rows, int nrt, int nslices) {
    extern __shared__ char sm[];
    uint32_t smb = smem_u32(sm);
    const int tid = threadIdx.x;
    const int wid = tid >> 5;
    const int lane = tid & 31;
    const int ct = blockIdx.x;
    const int slice = blockIdx.y;

    const uint32_t bufA[2] = {SM_A0, SM_A1};

    cp_tile(smb + SM_B, B + (size_t)ct * 128 * DIM_H, 128);
    cp_tile(smb + bufA[0], A + (size_t)slice * 128 * DIM_H,
            n_rows - slice * 128);
    CP_COMMIT();

    float* bias_s = reinterpret_cast<float*>(sm + SM_BIAS);
    if (tid < 128)
        bias_s[tid] = (ct == 0) ? (bias0 ? bias0[tid] : 0.f)
                                : (bias1 ? bias1[(ct - 1) * 128 + tid] : 0.f);

    const int wr = wid & 7;
    const int wc = wid >> 3;

    const int a_m = lane & 15;
    const int a_k = (lane >> 4) * 8;
    const uint32_t offA = (uint32_t)(((wr * 16 + a_m) * LDA + a_k) * 2);

    const int b_n = (lane & 7) + (lane >> 4) * 8;
    const int b_k = ((lane >> 3) & 1) * 8;
    uint32_t offB[4];
#pragma unroll
    for (int p = 0; p < 4; p++)
        offB[p] = (uint32_t)(((wc * 64 + p * 16 + b_n) * LDA + b_k) * 2);

    const int r_in = lane >> 2;
    const int c_in = (lane & 3) * 2;

    __half* Cp;
    int ldc, colbase;
    if (ct == 0) { Cp = C0; ldc = ldc0; colbase = 0; }
    else         { Cp = C1; ldc = ldc1; colbase = (ct - 1) * 128; }

    int nbuf = 0;
    for (int it = slice; it < nrt; it += nslices) {
        int next = it + nslices;
        __syncthreads();
        if (next < nrt) {
            cp_tile(smb + bufA[nbuf ^ 1], A + (size_t)next * 128 * DIM_H,
                    n_rows - next * 128);
            CP_COMMIT();
            CP_WAIT1();
        } else {
            CP_WAIT0();
        }
        __syncthreads();

        const uint32_t a_b = smb + bufA[nbuf];

        float acc[8][4];
#pragma unroll
        for (int nt = 0; nt < 8; nt++)
#pragma unroll
            for (int e = 0; e < 4; e++) acc[nt][e] = 0.f;

#pragma unroll
        for (int ks = 0; ks < 8; ks++) {
            const uint32_t kb = ks * 32;
            uint32_t a0, a1, a2, a3;
            ldsm_x4(a0, a1, a2, a3, a_b + offA + kb);
#pragma unroll
            for (int p = 0; p < 4; p++) {
                uint32_t b0, b1, b2, b3;
                ldsm_x4(b0, b1, b2, b3, smb + SM_B + offB[p] + kb);
                mma_f16(acc[2 * p],     a0, a1, a2, a3, b0, b1);
                mma_f16(acc[2 * p + 1], a0, a1, a2, a3, b2, b3);
            }
        }

        const int row_a = it * 128 + wr * 16 + r_in;
        const int row_b = row_a + 8;
#pragma unroll
        for (int nt = 0; nt < 8; nt++) {
            int cb = wc * 64 + nt * 8 + c_in;
            int cl = colbase + cb;
            float bx = bias_s[cb], by = bias_s[cb + 1];
            if (row_a < n_rows)
                *reinterpret_cast<__half2*>(Cp + (size_t)row_a * ldc + cl) =
                    __floats2half2_rn(acc[nt][0] + bx, acc[nt][1] + by);
            if (row_b < n_rows)
                *reinterpret_cast<__half2*>(Cp + (size_t)row_b * ldc + cl) =
                    __floats2half2_rn(acc[nt][2] + bx, acc[nt][3] + by);
        }
        nbuf ^= 1;
    }
}

// ---------------------------------------------------------------------------
// Edge scatter: TWO edges per warp (16 lanes each, 16B per lane).
// messages[dst] += fp16(T[src] + b_msg) via red.global.add.noftz.v4.f16x2
// (v4 = 128-bit, the max vector width ptxas accepts for f16x2 reductions).
// ---------------------------------------------------------------------------
__global__ void scatter_kernel(const int* __restrict__ esrc,
                               const int* __restrict__ edst,
                               const float* __restrict__ b_msg, int n_edges) {
    int gwarp = (blockIdx.x * blockDim.x + threadIdx.x) >> 5;
    int lane  = threadIdx.x & 31;
    int e = gwarp * 2 + (lane >> 4);
    int hl = lane & 15;
    if (e >= n_edges) return;
    int s = esrc[e];
    int d = edst[e];
    uint4 tv = *reinterpret_cast<const uint4*>(g_Th + (size_t)s * DIM_H + hl * 8);
    float4 b0 = *reinterpret_cast<const float4*>(b_msg + hl * 8);
    float4 b1 = *reinterpret_cast<const float4*>(b_msg + hl * 8 + 4);
    float bb[8] = {b0.x, b0.y, b0.z, b0.w, b1.x, b1.y, b1.z, b1.w};
    uint32_t tw[4] = {tv.x, tv.y, tv.z, tv.w};
    uint32_t r[4];
#pragma unroll
    for (int j = 0; j < 4; j++) {
        __half2 h = *reinterpret_cast<__half2*>(&tw[j]);
        float2 f = __half22float2(h);
        __half2 o = __floats2half2_rn(f.x + bb[2 * j], f.y + bb[2 * j + 1]);
        r[j] = *reinterpret_cast<uint32_t*>(&o);
    }
    __half* p = g_msg + (size_t)d * DIM_H + hl * 8;
    asm volatile("red.global.add.noftz.v4.f16x2 [%0], {%1, %2, %3, %4};"
                 :: "l"(p), "r"(r[0]), "r"(r[1]), "r"(r[2]), "r"(r[3])
                 : "memory");
}

// ---------------------------------------------------------------------------
// Fused GRU gates + LayerNorm + message residual. One warp per node.
// Also re-zeroes g_colsum for the next graph replay (block 0).
// ---------------------------------------------------------------------------
__device__ __forceinline__ float sigmoidf_(float x) {
    return 1.0f / (1.0f + expf(-x));
}

__global__ void gru_ln_kernel(const float* __restrict__ nodes,
                              const float* __restrict__ gamma,
                              const float* __restrict__ beta,
                              float* __restrict__ out, int n_nodes) {
    if (blockIdx.x == 0 && threadIdx.x < DIM_H)
        g_colsum[threadIdx.x] = 0.f;

    int gwarp = (blockIdx.x * blockDim.x + threadIdx.x) >> 5;
    int lane  = threadIdx.x & 31;
    if (gwarp >= n_nodes) return;

    size_t base = (size_t)gwarp * DIM_H;
    size_t gb   = (size_t)gwarp * DIM_3H;
    int le = lane * 4;

    float4 h4 = reinterpret_cast<const float4*>(nodes + base)[lane];

    float mm[4], ir[4], iz[4], in_[4], hr[4], hz[4], hn[4];
    ld4h(g_msg + base + le, mm);
    ld4h(g_gih + gb + le, ir);
    ld4h(g_gih + gb + 128 + le, iz);
    ld4h(g_gih + gb + 256 + le, in_);
    ld4h(g_ghh + gb + le, hr);
    ld4h(g_ghh + gb + 128 + le, hz);
    ld4h(g_ghh + gb + 256 + le, hn);

    float hh[4] = {h4.x, h4.y, h4.z, h4.w};

    float hx[4];
    float s = 0.f, s2 = 0.f;
#pragma unroll
    for (int c = 0; c < 4; c++) {
        float r = sigmoidf_(ir[c] + hr[c]);
        float z = sigmoidf_(iz[c] + hz[c]);
        float n = tanhf(in_[c] + r * hn[c]);
        hx[c] = (1.0f - z) * n + z * hh[c];
        s  += hx[c];
        s2 += hx[c] * hx[c];
    }
#pragma unroll
    for (int off = 16; off > 0; off >>= 1) {
        s  += __shfl_xor_sync(0xFFFFFFFF, s,  off);
        s2 += __shfl_xor_sync(0xFFFFFFFF, s2, off);
    }
    float mu   = s  * (1.0f / DIM_H);
    float var  = s2 * (1.0f / DIM_H) - mu * mu;
    float rstd = rsqrtf(var + LN_EPS);

    float4 g4 = reinterpret_cast<const float4*>(gamma)[lane];
    float4 b4 = reinterpret_cast<const float4*>(beta)[lane];
    float gg[4] = {g4.x, g4.y, g4.z, g4.w};
    float bb[4] = {b4.x, b4.y, b4.z, b4.w};

    float o[4];
#pragma unroll
    for (int c = 0; c < 4; c++)
        o[c] = gg[c] * (hx[c] - mu) * rstd + bb[c] + mm[c];

    reinterpret_cast<float4*>(out + base)[lane] =
        make_float4(o[0], o[1], o[2], o[3]);
}

// ---------------------------------------------------------------------------
// Launch. Graph:
//   main: prep -> gemmT -> scatter -> [wait evB] gemm2 -> [wait evJoin] gru_ln
//   s2:   [wait evFork] bias2 (evB) -> gemmGH (evJoin)
// ---------------------------------------------------------------------------
extern "C" void kernel_launch(void* const* d_in, const int* in_sizes, int n_in,
                              void* d_out, int out_size) {
    const float* nodes = (const float*)d_in[0];
    const float* W_msg = (const float*)d_in[1];
    const float* b_msg = (const float*)d_in[2];
    const float* w_ih  = (const float*)d_in[3];
    const float* w_hh  = (const float*)d_in[4];
    const float* b_ih  = (const float*)d_in[5];
    const float* b_hh  = (const float*)d_in[6];
    const float* gamma = (const float*)d_in[7];
    const float* beta  = (const float*)d_in[8];
    const int*   esrc  = (const int*)d_in[9];
    const int*   edst  = (const int*)d_in[10];
    float* out = (float*)d_out;

    int n_nodes = in_sizes[0] / DIM_H;
    int n_edges = in_sizes[9];

    float *pBias2;
    __half *pMsg, *pTh, *pGhh, *pGih, *pNh, *pWc, *pWi;
    cudaGetSymbolAddress((void**)&pBias2, g_bias2);
    cudaGetSymbolAddress((void**)&pMsg, g_msg);
    cudaGetSymbolAddress((void**)&pTh,  g_Th);
    cudaGetSymbolAddress((void**)&pGhh, g_ghh);
    cudaGetSymbolAddress((void**)&pGih, g_gih);
    cudaGetSymbolAddress((void**)&pNh,  g_nh);
    cudaGetSymbolAddress((void**)&pWc,  g_Wcat);
    cudaGetSymbolAddress((void**)&pWi,  g_Wih);

    cudaFuncSetAttribute(gemm_ws,
                         cudaFuncAttributeMaxDynamicSharedMemorySize, SM_TOTAL);

    static cudaStream_t s2 = nullptr;
    static cudaEvent_t evFork = nullptr, evB = nullptr, evJoin = nullptr;
    if (s2 == nullptr) {
        cudaStreamCreateWithFlags(&s2, cudaStreamNonBlocking);
        cudaEventCreateWithFlags(&evFork, cudaEventDisableTiming);
        cudaEventCreateWithFlags(&evB, cudaEventDisableTiming);
        cudaEventCreateWithFlags(&evJoin, cudaEventDisableTiming);
    }

    int nrt = (n_nodes + 127) / 128;
    int n8 = n_nodes * DIM_H / 8;
    int nbN = (n8 + 255) / 256;
    int nbW = (14336 + 255) / 256;

    // 1: fused prep (weights + nodes convert + msg zero + colsum)
    prep_kernel<<<nbN + nbW, 256>>>(nodes, W_msg, w_hh, w_ih, n8, nbN);

    // Fork side stream: bias2 then gemmGH
    cudaEventRecord(evFork, 0);
    cudaStreamWaitEvent(s2, evFork, 0);
    bias2_fast<<<12, 1024, 0, s2>>>(w_ih, b_ih, n_nodes);
    cudaEventRecord(evB, s2);
    gemm_ws<<<dim3(3, 49), 512, SM_TOTAL, s2>>>(
        pNh, pWc + 128 * DIM_H, b_hh, b_hh + 128,
        pGhh, DIM_3H, pGhh + 128, DIM_3H, n_nodes, nrt, 49);
    cudaEventRecord(evJoin, s2);

    // Main: T = nodes @ W_msg^T (one wave)
    gemm_ws<<<dim3(1, 148), 512, SM_TOTAL>>>(pNh, pWc, nullptr, nullptr,
                                             pTh, DIM_H, pTh, DIM_H,
                                             n_nodes, nrt, 148);
    // messages[dst] += T[src] + b_msg   (v4.f16x2 reductions)
    scatter_kernel<<<((n_edges + 1) / 2 * 32 + 255) / 256, 256>>>(
        esrc, edst, b_msg, n_edges);

    // gi = msg @ w_ih^T + bias2  (needs bias2 from s2)
    cudaStreamWaitEvent(0, evB, 0);
    gemm_ws<<<dim3(3, 49), 512, SM_TOTAL>>>(pMsg, pWi, pBias2, pBias2 + 128,
                                            pGih, DIM_3H, pGih + 128, DIM_3H,
                                            n_nodes, nrt, 49);

    // gru_ln needs gh from s2
    cudaStreamWaitEvent(0, evJoin, 0);
    gru_ln_kernel<<<(n_nodes + 7) / 8, 256>>>(nodes, gamma, beta, out, n_nodes);
}